// round 1
// baseline (speedup 1.0000x reference)
#include <cuda_runtime.h>
#include <math.h>

#define B_   4
#define SQ_  1024
#define SKV_ 1024
#define M_   8
#define D_   64
#define H_   8
#define F_   64
#define BH_  (B_*H_)

// ---------------- scratch (device globals; no allocation) ----------------
__device__ float g_Wqf[H_*D_*F_];                    // combined Wq^T @ freq  [h][d][f]
__device__ float g_Wkf[H_*D_*F_];
__device__ float g_qrff[(size_t)BH_*SQ_*2*F_];       // [bh][s][128]
__device__ float g_krff[(size_t)BH_*SKV_*2*F_];
__device__ float g_va  [(size_t)BH_*SKV_*M_*D_];     // [bh][s][m*64+e]
__device__ float g_scores[(size_t)BH_*SQ_*SKV_];     // [bh][q][k] -> attn in place
__device__ float g_out [(size_t)BH_*SQ_*M_*D_];      // [bh][q][m*64+e]

// ---------------- K1: combined projection-RFF matrices ----------------
// Wqf[h,d,f] = sum_e Wq[h*64+e, d] * (base[h,e,f] * exp(-log_bw[h]))
__global__ __launch_bounds__(256) void k_combine(const float* __restrict__ Wq,
                                                 const float* __restrict__ Wk,
                                                 const float* __restrict__ base,
                                                 const float* __restrict__ log_bw) {
    __shared__ float sWq[64*64], sWk[64*64], sB[64*64];
    int h = blockIdx.x;
    float inv = expf(-log_bw[h]);
    for (int i = threadIdx.x; i < 4096; i += 256) {
        sWq[i] = Wq[h*4096 + i];          // [e][d]
        sWk[i] = Wk[h*4096 + i];
        sB[i]  = base[h*4096 + i] * inv;  // [e][f]
    }
    __syncthreads();
    for (int idx = threadIdx.x; idx < 4096; idx += 256) {
        int d = idx >> 6, f = idx & 63;
        float aq = 0.f, ak = 0.f;
        #pragma unroll
        for (int e = 0; e < 64; e++) {
            float bf = sB[e*64 + f];
            aq = fmaf(sWq[e*64 + d], bf, aq);
            ak = fmaf(sWk[e*64 + d], bf, ak);
        }
        g_Wqf[h*4096 + d*64 + f] = aq;
        g_Wkf[h*4096 + d*64 + f] = ak;
    }
}

// ---------------- K2: fused projection + RFF encode ----------------
// out_rff[bh][s][f]    = sum_m w[s,m] * cos(proj) * RFF_SCALE
// out_rff[bh][s][64+f] = sum_m w[s,m] * sin(proj) * RFF_SCALE
// proj = sum_d atoms[b,s,m,d] * Wf[h,d,f]
__global__ __launch_bounds__(256) void k_rff(const float* __restrict__ atoms,
                                             const float* __restrict__ weights,
                                             int is_q) {
    __shared__ float sW[64*64];         // [d][f]
    __shared__ float sAt[4][8][64];
    __shared__ float sw[4][8];
    int bh = blockIdx.y;
    int b = bh >> 3, h = bh & 7;
    const float* Wf = is_q ? g_Wqf : g_Wkf;
    float* dstbase = (is_q ? g_qrff : g_krff);
    for (int i = threadIdx.x; i < 4096; i += 256) sW[i] = Wf[h*4096 + i];
    int s0 = blockIdx.x * 16;
    int f  = threadIdx.x & 63;
    int sl = threadIdx.x >> 6;
    for (int ss = 0; ss < 16; ss += 4) {
        __syncthreads();
        for (int i = threadIdx.x; i < 2048; i += 256) {
            int si = i >> 9;          // 0..3
            int md = i & 511;         // m*64+d
            sAt[si][md >> 6][md & 63] =
                atoms[(size_t)(b*1024 + s0 + ss + si)*512 + md];
        }
        if (threadIdx.x < 32) {
            int si = threadIdx.x >> 3, m = threadIdx.x & 7;
            sw[si][m] = weights[(b*1024 + s0 + ss + si)*8 + m];
        }
        __syncthreads();
        float ac = 0.f, asn = 0.f;
        #pragma unroll
        for (int m = 0; m < 8; m++) {
            float p = 0.f;
            #pragma unroll
            for (int d = 0; d < 64; d++)
                p = fmaf(sAt[sl][m][d], sW[d*64 + f], p);
            float sv, cv;
            sincosf(p, &sv, &cv);
            float w = sw[sl][m];
            ac  = fmaf(w, cv, ac);
            asn = fmaf(w, sv, asn);
        }
        int s = s0 + ss + sl;
        float* dst = dstbase + ((size_t)bh*1024 + s)*128;
        dst[f]      = ac  * 0.125f;
        dst[64 + f] = asn * 0.125f;
    }
}

// ---------------- K3: va projection (NT GEMM, K=64) ----------------
// rows r=(b,s,m) over 32768, cols c=(h,e) over 512
// va[((b*8+h)*1024+s)*512 + m*64+e] = sum_d v_atoms[r*64+d] * Wv[c*64+d]
__global__ __launch_bounds__(256) void k_va(const float* __restrict__ v_atoms,
                                            const float* __restrict__ Wv) {
    __shared__ float sA[64][65];   // [row][d]
    __shared__ float sB[64][65];   // [col][d]
    int rb = blockIdx.y * 64, cb = blockIdx.x * 64;
    for (int i = threadIdx.x; i < 4096; i += 256) {
        int r = i >> 6, d = i & 63;
        sA[r][d] = v_atoms[(size_t)(rb + r)*64 + d];
        sB[r][d] = Wv[(cb + r)*64 + d];
    }
    __syncthreads();
    int tx = threadIdx.x & 15, ty = threadIdx.x >> 4;
    float acc[4][4] = {};
    #pragma unroll
    for (int k = 0; k < 64; k++) {
        float a[4], bb[4];
        #pragma unroll
        for (int i = 0; i < 4; i++) a[i]  = sA[ty*4 + i][k];
        #pragma unroll
        for (int j = 0; j < 4; j++) bb[j] = sB[tx*4 + j][k];
        #pragma unroll
        for (int i = 0; i < 4; i++)
            #pragma unroll
            for (int j = 0; j < 4; j++)
                acc[i][j] = fmaf(a[i], bb[j], acc[i][j]);
    }
    #pragma unroll
    for (int i = 0; i < 4; i++) {
        int r = rb + ty*4 + i;
        int b = r >> 13, s = (r >> 3) & 1023, m = r & 7;
        #pragma unroll
        for (int j = 0; j < 4; j++) {
            int c = cb + tx*4 + j;
            int h = c >> 6, e = c & 63;
            g_va[(size_t)((b*8 + h)*1024 + s)*512 + m*64 + e] = acc[i][j];
        }
    }
}

// ---------------- K4: scores NT GEMM (K=128) + temperature ----------------
__global__ __launch_bounds__(256) void k_scores(const float* __restrict__ log_temp) {
    int bh = blockIdx.z;
    float temp = expf(log_temp[bh & 7]);
    const float* A  = g_qrff + (size_t)bh*1024*128;
    const float* Bm = g_krff + (size_t)bh*1024*128;
    __shared__ float sA[64][33], sB[64][33];
    int qb = blockIdx.y * 64, kb = blockIdx.x * 64;
    int tx = threadIdx.x & 15, ty = threadIdx.x >> 4;
    float acc[4][4] = {};
    for (int kc = 0; kc < 128; kc += 32) {
        __syncthreads();
        for (int i = threadIdx.x; i < 2048; i += 256) {
            int r = i >> 5, c = i & 31;
            sA[r][c] = A [(size_t)(qb + r)*128 + kc + c];
            sB[r][c] = Bm[(size_t)(kb + r)*128 + kc + c];
        }
        __syncthreads();
        #pragma unroll
        for (int k = 0; k < 32; k++) {
            float a[4], bb[4];
            #pragma unroll
            for (int i = 0; i < 4; i++) a[i]  = sA[ty*4 + i][k];
            #pragma unroll
            for (int j = 0; j < 4; j++) bb[j] = sB[tx*4 + j][k];
            #pragma unroll
            for (int i = 0; i < 4; i++)
                #pragma unroll
                for (int j = 0; j < 4; j++)
                    acc[i][j] = fmaf(a[i], bb[j], acc[i][j]);
        }
    }
    float* C = g_scores + (size_t)bh*1024*1024;
    #pragma unroll
    for (int i = 0; i < 4; i++)
        #pragma unroll
        for (int j = 0; j < 4; j++)
            C[(size_t)(qb + ty*4 + i)*1024 + kb + tx*4 + j] = acc[i][j] * temp;
}

// ---------------- K5: row softmax over 1024 (in place) ----------------
__global__ __launch_bounds__(256) void k_softmax() {
    __shared__ float red[8];
    size_t row = blockIdx.x;
    float4* p = (float4*)(g_scores + row*1024);
    int t = threadIdx.x;
    float4 v = p[t];
    float mx = fmaxf(fmaxf(v.x, v.y), fmaxf(v.z, v.w));
    #pragma unroll
    for (int o = 16; o; o >>= 1) mx = fmaxf(mx, __shfl_xor_sync(~0u, mx, o));
    if ((t & 31) == 0) red[t >> 5] = mx;
    __syncthreads();
    float rm = red[0];
    #pragma unroll
    for (int i = 1; i < 8; i++) rm = fmaxf(rm, red[i]);
    v.x = __expf(v.x - rm); v.y = __expf(v.y - rm);
    v.z = __expf(v.z - rm); v.w = __expf(v.w - rm);
    float s = v.x + v.y + v.z + v.w;
    #pragma unroll
    for (int o = 16; o; o >>= 1) s += __shfl_xor_sync(~0u, s, o);
    __syncthreads();
    if ((t & 31) == 0) red[t >> 5] = s;
    __syncthreads();
    float tot = 0.f;
    #pragma unroll
    for (int i = 0; i < 8; i++) tot += red[i];
    float inv = 1.0f / tot;
    v.x *= inv; v.y *= inv; v.z *= inv; v.w *= inv;
    p[t] = v;
}

// ---------------- K6: out = attn @ va  (128x128 tile, 8x8 microtile) ----------------
__global__ __launch_bounds__(256) void k_out() {
    int bh = blockIdx.z;
    const float* A  = g_scores + (size_t)bh*1024*1024;
    const float* Bm = g_va     + (size_t)bh*1024*512;
    float*       C  = g_out    + (size_t)bh*1024*512;
    int mb = blockIdx.y * 128, nb = blockIdx.x * 128;
    __shared__ float sA[8][128];
    __shared__ float sB[8][128];
    int tid = threadIdx.x;
    int arow = tid >> 1, acol4 = (tid & 1) * 4;
    int brow = tid >> 5, bcol  = (tid * 4) & 127;
    int ty = tid >> 4, tx = tid & 15;
    float acc[8][8] = {};
    for (int kc = 0; kc < 1024; kc += 8) {
        __syncthreads();
        float4 av = *(const float4*)&A[(size_t)(mb + arow)*1024 + kc + acol4];
        sA[acol4 + 0][arow] = av.x; sA[acol4 + 1][arow] = av.y;
        sA[acol4 + 2][arow] = av.z; sA[acol4 + 3][arow] = av.w;
        *(float4*)&sB[brow][bcol] =
            *(const float4*)&Bm[(size_t)(kc + brow)*512 + nb + bcol];
        __syncthreads();
        #pragma unroll
        for (int k = 0; k < 8; k++) {
            float a[8], bb[8];
            *(float4*)&a[0]  = *(float4*)&sA[k][ty*4];
            *(float4*)&a[4]  = *(float4*)&sA[k][64 + ty*4];
            *(float4*)&bb[0] = *(float4*)&sB[k][tx*4];
            *(float4*)&bb[4] = *(float4*)&sB[k][64 + tx*4];
            #pragma unroll
            for (int i = 0; i < 8; i++)
                #pragma unroll
                for (int j = 0; j < 8; j++)
                    acc[i][j] = fmaf(a[i], bb[j], acc[i][j]);
        }
    }
    #pragma unroll
    for (int i = 0; i < 8; i++) {
        int r = mb + ((i < 4) ? (ty*4 + i) : (64 + ty*4 + i - 4));
        #pragma unroll
        for (int j = 0; j < 8; j++) {
            int c = nb + ((j < 4) ? (tx*4 + j) : (64 + tx*4 + j - 4));
            C[(size_t)r*512 + c] = acc[i][j];
        }
    }
}

// ---------------- K7: output projection out_atoms = gather(out) @ Wo^T ----------------
// rows r=(b,q,m) over 32768, cols d over 64, K = 512 = (h,e)
__global__ __launch_bounds__(256) void k_oproj(const float* __restrict__ Wo,
                                               float* __restrict__ out_atoms) {
    __shared__ float sA[64][65];   // [row][e]  for current h
    __shared__ float sB[64][65];   // [d][e]
    int rb = blockIdx.x * 64;
    int tx = threadIdx.x & 15, ty = threadIdx.x >> 4;
    float acc[4][4] = {};
    for (int h = 0; h < 8; h++) {
        __syncthreads();
        for (int i = threadIdx.x; i < 4096; i += 256) {
            int r = i >> 6, e = i & 63;
            int gr = rb + r;
            int b = gr >> 13, q = (gr >> 3) & 1023, m = gr & 7;
            sA[r][e] = g_out[(size_t)((b*8 + h)*1024 + q)*512 + m*64 + e];
            sB[r][e] = Wo[r*512 + h*64 + e];   // r plays role of d
        }
        __syncthreads();
        #pragma unroll
        for (int k = 0; k < 64; k++) {
            float a[4], bb[4];
            #pragma unroll
            for (int i = 0; i < 4; i++) a[i]  = sA[ty*4 + i][k];
            #pragma unroll
            for (int j = 0; j < 4; j++) bb[j] = sB[tx*4 + j][k];
            #pragma unroll
            for (int i = 0; i < 4; i++)
                #pragma unroll
                for (int j = 0; j < 4; j++)
                    acc[i][j] = fmaf(a[i], bb[j], acc[i][j]);
        }
    }
    #pragma unroll
    for (int i = 0; i < 4; i++)
        #pragma unroll
        for (int j = 0; j < 4; j++)
            out_atoms[(size_t)(rb + ty*4 + i)*64 + tx*4 + j] = acc[i][j];
}

// ---------------- K8: log-weight update ----------------
__global__ __launch_bounds__(64) void k_lw(const float* __restrict__ Ww,
                                           const float* __restrict__ qlw,
                                           const float* __restrict__ out_atoms,
                                           float* __restrict__ out2) {
    __shared__ float mean[64];
    int bq = blockIdx.x;          // 0..4095 = (b,q)
    int t = threadIdx.x;          // 64 threads, one per d
    float s = 0.f;
    #pragma unroll
    for (int m = 0; m < 8; m++)
        s += out_atoms[(size_t)(bq*8 + m)*64 + t];
    mean[t] = s * 0.125f;
    __syncthreads();
    if (t < 8) {
        float acc = 0.f;
        #pragma unroll
        for (int d = 0; d < 64; d++)
            acc = fmaf(mean[d], Ww[t*64 + d], acc);
        out2[bq*8 + t] = qlw[bq*8 + t] + acc;
    }
}

// ---------------- launch ----------------
extern "C" void kernel_launch(void* const* d_in, const int* in_sizes, int n_in,
                              void* d_out, int out_size) {
    const float* q_atoms   = (const float*)d_in[0];
    const float* q_weights = (const float*)d_in[1];
    const float* q_logw    = (const float*)d_in[2];
    const float* k_atoms   = (const float*)d_in[3];
    const float* k_weights = (const float*)d_in[4];
    const float* v_atoms   = (const float*)d_in[5];
    const float* Wq        = (const float*)d_in[6];
    const float* Wk        = (const float*)d_in[7];
    const float* Wv        = (const float*)d_in[8];
    const float* Wo        = (const float*)d_in[9];
    const float* Ww        = (const float*)d_in[10];
    const float* log_bw    = (const float*)d_in[11];
    const float* log_temp  = (const float*)d_in[12];
    const float* rff_base  = (const float*)d_in[13];

    float* out_atoms = (float*)d_out;                       // [B,SQ,M,D]
    float* out_lw    = (float*)d_out + (size_t)B_*SQ_*M_*D_; // [B,SQ,M]

    k_combine<<<H_, 256>>>(Wq, Wk, rff_base, log_bw);
    k_rff<<<dim3(SQ_/16,  BH_), 256>>>(q_atoms, q_weights, 1);
    k_rff<<<dim3(SKV_/16, BH_), 256>>>(k_atoms, k_weights, 0);
    k_va<<<dim3(8, 512), 256>>>(v_atoms, Wv);
    k_scores<<<dim3(16, 16, BH_), 256>>>(log_temp);
    k_softmax<<<BH_*SQ_, 256>>>();
    k_out<<<dim3(4, 8, BH_), 256>>>();
    k_oproj<<<512, 256>>>(Wo, out_atoms);
    k_lw<<<B_*SQ_, 64>>>(Ww, q_logw, out_atoms, out_lw);
}

// round 4
// speedup vs baseline: 1.9175x; 1.9175x over previous
#include <cuda_runtime.h>
#include <cuda_fp16.h>
#include <cstdint>
#include <math.h>

#define B_   4
#define SQ_  1024
#define SKV_ 1024
#define M_   8
#define D_   64
#define H_   8
#define F_   64
#define BH_  (B_*H_)

// ---------------- scratch (device globals; no allocation) ----------------
__device__ float  g_Wqf[H_*D_*F_];
__device__ float  g_Wkf[H_*D_*F_];
__device__ __half g_qrff[(size_t)BH_*SQ_*2*F_];      // [bh][q][128]
__device__ __half g_krff[(size_t)BH_*SKV_*2*F_];     // [bh][k][128]
__device__ __half g_vaT [(size_t)BH_*512*SKV_];      // [bh][n][s]  (K-contiguous)
__device__ float  g_scores[(size_t)BH_*SQ_*SKV_];    // fp32 logits
__device__ __half g_attn[(size_t)BH_*SQ_*SKV_];      // half attn
__device__ float  g_out [(size_t)BH_*SQ_*M_*D_];     // [bh][q][m*64+e]

__device__ __forceinline__ uint32_t s2u(const void* p) {
    uint32_t a;
    asm("{ .reg .u64 t; cvta.to.shared.u64 t, %1; cvt.u32.u64 %0, t; }" : "=r"(a) : "l"(p));
    return a;
}

// ---------------- K1: combined projection-RFF matrices ----------------
__global__ __launch_bounds__(256) void k_combine(const float* __restrict__ Wq,
                                                 const float* __restrict__ Wk,
                                                 const float* __restrict__ base,
                                                 const float* __restrict__ log_bw) {
    __shared__ float sWq[64*64], sWk[64*64], sB[64*64];
    int h = blockIdx.x;
    float inv = expf(-log_bw[h]);
    for (int i = threadIdx.x; i < 4096; i += 256) {
        sWq[i] = Wq[h*4096 + i];
        sWk[i] = Wk[h*4096 + i];
        sB[i]  = base[h*4096 + i] * inv;
    }
    __syncthreads();
    for (int idx = threadIdx.x; idx < 4096; idx += 256) {
        int d = idx >> 6, f = idx & 63;
        float aq = 0.f, ak = 0.f;
        #pragma unroll
        for (int e = 0; e < 64; e++) {
            float bf = sB[e*64 + f];
            aq = fmaf(sWq[e*64 + d], bf, aq);
            ak = fmaf(sWk[e*64 + d], bf, ak);
        }
        g_Wqf[h*4096 + d*64 + f] = aq;
        g_Wkf[h*4096 + d*64 + f] = ak;
    }
}

// ---------------- K2: fused projection + RFF encode (half out) ----------------
__global__ __launch_bounds__(256) void k_rff(const float* __restrict__ atoms,
                                             const float* __restrict__ weights,
                                             int is_q) {
    __shared__ float sW[64*64];
    __shared__ float sAt[4][8][64];
    __shared__ float sw[4][8];
    int bh = blockIdx.y;
    int b = bh >> 3, h = bh & 7;
    const float* Wf = is_q ? g_Wqf : g_Wkf;
    __half* dstbase = (is_q ? g_qrff : g_krff);
    for (int i = threadIdx.x; i < 4096; i += 256) sW[i] = Wf[h*4096 + i];
    int s0 = blockIdx.x * 16;
    int f  = threadIdx.x & 63;
    int sl = threadIdx.x >> 6;
    for (int ss = 0; ss < 16; ss += 4) {
        __syncthreads();
        for (int i = threadIdx.x; i < 2048; i += 256) {
            int si = i >> 9;
            int md = i & 511;
            sAt[si][md >> 6][md & 63] =
                atoms[(size_t)(b*1024 + s0 + ss + si)*512 + md];
        }
        if (threadIdx.x < 32) {
            int si = threadIdx.x >> 3, m = threadIdx.x & 7;
            sw[si][m] = weights[(b*1024 + s0 + ss + si)*8 + m];
        }
        __syncthreads();
        float ac = 0.f, asn = 0.f;
        #pragma unroll
        for (int m = 0; m < 8; m++) {
            float p = 0.f;
            #pragma unroll
            for (int d = 0; d < 64; d++)
                p = fmaf(sAt[sl][m][d], sW[d*64 + f], p);
            float sv, cv;
            __sincosf(p, &sv, &cv);
            float w = sw[sl][m];
            ac  = fmaf(w, cv, ac);
            asn = fmaf(w, sv, asn);
        }
        int s = s0 + ss + sl;
        __half* dst = dstbase + ((size_t)bh*1024 + s)*128;
        dst[f]      = __float2half(ac  * 0.125f);
        dst[64 + f] = __float2half(asn * 0.125f);
    }
}

// ---------------- K3: va projection -> transposed half vaT[bh][n][s] ----------------
__global__ __launch_bounds__(256) void k_va(const float* __restrict__ v_atoms,
                                            const float* __restrict__ Wv) {
    __shared__ float sA[64][65];
    __shared__ float sB[64][65];
    __shared__ __align__(16) __half sT[512][8];
    int rb = blockIdx.y * 64, cb = blockIdx.x * 64;
    for (int i = threadIdx.x; i < 4096; i += 256) {
        int r = i >> 6, d = i & 63;
        sA[r][d] = v_atoms[(size_t)(rb + r)*64 + d];
        sB[r][d] = Wv[(cb + r)*64 + d];
    }
    __syncthreads();
    int tx = threadIdx.x & 15, ty = threadIdx.x >> 4;
    float acc[4][4] = {};
    #pragma unroll
    for (int k = 0; k < 64; k++) {
        float a[4], bb[4];
        #pragma unroll
        for (int i = 0; i < 4; i++) a[i]  = sA[ty*4 + i][k];
        #pragma unroll
        for (int j = 0; j < 4; j++) bb[j] = sB[tx*4 + j][k];
        #pragma unroll
        for (int i = 0; i < 4; i++)
            #pragma unroll
            for (int j = 0; j < 4; j++)
                acc[i][j] = fmaf(a[i], bb[j], acc[i][j]);
    }
    #pragma unroll
    for (int i = 0; i < 4; i++) {
        int k = ty*4 + i;
        int slcl = k >> 3, m = k & 7;
        #pragma unroll
        for (int j = 0; j < 4; j++) {
            int e = tx*4 + j;
            sT[m*64 + e][slcl] = __float2half(acc[i][j]);
        }
    }
    __syncthreads();
    int b = rb >> 13, s0 = (rb >> 3) & 1023;
    int h = cb >> 6;
    int bh = b*8 + h;
    for (int n = threadIdx.x; n < 512; n += 256) {
        *(uint4*)&g_vaT[((size_t)bh*512 + n)*1024 + s0] = *(const uint4*)&sT[n][0];
    }
}

// ---------------- K4/K6: mma.sync GEMM (SC=true: scores, SC=false: attn@va) ----------------
// C[q][n] = sum_k A[q][k]*B[n][k]; 128x128 block tile, KC=32 double-buffered.
template<bool SC>
__global__ __launch_bounds__(256) void k_mma(const float* __restrict__ log_temp) {
    constexpr int NCHUNK = SC ? 4 : 32;                 // K = NCHUNK*32
    constexpr int ASTR   = SC ? 128 : 1024;
    constexpr int BSTR   = SC ? 128 : 1024;
    constexpr int BROWS  = SC ? 1024 : 512;
    constexpr int CSTR   = SC ? 1024 : 512;
    const __half* Ag = SC ? g_qrff : g_attn;
    const __half* Bg = SC ? g_krff : g_vaT;
    float*        Cg = SC ? g_scores : g_out;

    __shared__ __align__(16) __half sA[2][128][40];
    __shared__ __align__(16) __half sB[2][128][40];

    int tid = threadIdx.x, wid = tid >> 5, lid = tid & 31;
    int bh = blockIdx.z;
    int qb = blockIdx.y * 128, nb = blockIdx.x * 128;
    const __half* Ab = Ag + (size_t)bh*1024*ASTR + (size_t)qb*ASTR;
    const __half* Bb = Bg + (size_t)bh*BROWS*BSTR + (size_t)nb*BSTR;

    int warp_m = (wid & 3) * 32;
    int warp_n = (wid >> 2) * 64;
    float acc[2][8][4] = {};

    auto load = [&](int st, int kc) {
        #pragma unroll
        for (int i = 0; i < 2; i++) {
            int id = tid + i*256;              // 0..511
            int row = id >> 2, c = id & 3;
            uint32_t d = s2u(&sA[st][row][c*8]);
            asm volatile("cp.async.cg.shared.global [%0], [%1], 16;"
                         :: "r"(d), "l"(Ab + (size_t)row*ASTR + kc + c*8));
        }
        #pragma unroll
        for (int i = 0; i < 2; i++) {
            int id = tid + i*256;
            int row = id >> 2, c = id & 3;
            uint32_t d = s2u(&sB[st][row][c*8]);
            asm volatile("cp.async.cg.shared.global [%0], [%1], 16;"
                         :: "r"(d), "l"(Bb + (size_t)row*BSTR + kc + c*8));
        }
        asm volatile("cp.async.commit_group;" ::: "memory");
    };

    load(0, 0);
    load(1, 32);

    for (int c = 0; c < NCHUNK; c++) {
        int st = c & 1;
        if (c + 2 < NCHUNK) asm volatile("cp.async.wait_group 1;" ::: "memory");
        else                asm volatile("cp.async.wait_group 0;" ::: "memory");
        __syncthreads();

        #pragma unroll
        for (int kk = 0; kk < 32; kk += 16) {
            uint32_t af[2][4];
            #pragma unroll
            for (int mi = 0; mi < 2; mi++) {
                uint32_t addr = s2u(&sA[st][warp_m + mi*16 + (lid & 15)][kk + ((lid >> 4) << 3)]);
                asm volatile("ldmatrix.sync.aligned.m8n8.x4.shared.b16 {%0,%1,%2,%3}, [%4];"
                    : "=r"(af[mi][0]), "=r"(af[mi][1]), "=r"(af[mi][2]), "=r"(af[mi][3])
                    : "r"(addr));
            }
            uint32_t bf[8][2];
            #pragma unroll
            for (int nj = 0; nj < 4; nj++) {
                int n = warp_n + nj*16 + ((lid >> 4) << 3) + (lid & 7);
                int k = kk + (((lid >> 3) & 1) << 3);
                uint32_t addr = s2u(&sB[st][n][k]);
                uint32_t r0, r1, r2, r3;
                asm volatile("ldmatrix.sync.aligned.m8n8.x4.shared.b16 {%0,%1,%2,%3}, [%4];"
                    : "=r"(r0), "=r"(r1), "=r"(r2), "=r"(r3) : "r"(addr));
                bf[nj*2][0]   = r0; bf[nj*2][1]   = r1;
                bf[nj*2+1][0] = r2; bf[nj*2+1][1] = r3;
            }
            #pragma unroll
            for (int mi = 0; mi < 2; mi++)
                #pragma unroll
                for (int ni = 0; ni < 8; ni++)
                    asm volatile("mma.sync.aligned.m16n8k16.row.col.f32.f16.f16.f32 "
                        "{%0,%1,%2,%3}, {%4,%5,%6,%7}, {%8,%9}, {%0,%1,%2,%3};"
                        : "+f"(acc[mi][ni][0]), "+f"(acc[mi][ni][1]),
                          "+f"(acc[mi][ni][2]), "+f"(acc[mi][ni][3])
                        : "r"(af[mi][0]), "r"(af[mi][1]), "r"(af[mi][2]), "r"(af[mi][3]),
                          "r"(bf[ni][0]), "r"(bf[ni][1]));
        }
        __syncthreads();
        if (c + 2 < NCHUNK) load(st, (c + 2)*32);
    }

    float scale = SC ? __expf(log_temp[bh & 7]) : 1.f;
    #pragma unroll
    for (int mi = 0; mi < 2; mi++) {
        #pragma unroll
        for (int ni = 0; ni < 8; ni++) {
            int row = qb + warp_m + mi*16 + (lid >> 2);
            int col = nb + warp_n + ni*8 + (lid & 3)*2;
            float* Cp = Cg + (size_t)bh*1024*CSTR + (size_t)row*CSTR + col;
            Cp[0]          = acc[mi][ni][0] * scale;
            Cp[1]          = acc[mi][ni][1] * scale;
            Cp[(size_t)CSTR*8]     = acc[mi][ni][2] * scale;
            Cp[(size_t)CSTR*8 + 1] = acc[mi][ni][3] * scale;
        }
    }
}

// ---------------- K5: row softmax (fp32 in, half out) ----------------
__global__ __launch_bounds__(256) void k_softmax() {
    __shared__ float red[8];
    size_t row = blockIdx.x;
    const float4* p = (const float4*)(g_scores + row*1024);
    int t = threadIdx.x;
    float4 v = p[t];
    float mx = fmaxf(fmaxf(v.x, v.y), fmaxf(v.z, v.w));
    #pragma unroll
    for (int o = 16; o; o >>= 1) mx = fmaxf(mx, __shfl_xor_sync(~0u, mx, o));
    if ((t & 31) == 0) red[t >> 5] = mx;
    __syncthreads();
    float rm = red[0];
    #pragma unroll
    for (int i = 1; i < 8; i++) rm = fmaxf(rm, red[i]);
    v.x = __expf(v.x - rm); v.y = __expf(v.y - rm);
    v.z = __expf(v.z - rm); v.w = __expf(v.w - rm);
    float s = v.x + v.y + v.z + v.w;
    #pragma unroll
    for (int o = 16; o; o >>= 1) s += __shfl_xor_sync(~0u, s, o);
    __syncthreads();
    if ((t & 31) == 0) red[t >> 5] = s;
    __syncthreads();
    float tot = 0.f;
    #pragma unroll
    for (int i = 0; i < 8; i++) tot += red[i];
    float inv = 1.0f / tot;
    __half2* o2 = (__half2*)(g_attn + row*1024);
    o2[2*t]     = __floats2half2_rn(v.x * inv, v.y * inv);
    o2[2*t + 1] = __floats2half2_rn(v.z * inv, v.w * inv);
}

// ---------------- K7: output projection ----------------
__global__ __launch_bounds__(256) void k_oproj(const float* __restrict__ Wo,
                                               float* __restrict__ out_atoms) {
    __shared__ float sA[64][65];
    __shared__ float sB[64][65];
    int rb = blockIdx.x * 64;
    int tx = threadIdx.x & 15, ty = threadIdx.x >> 4;
    float acc[4][4] = {};
    for (int h = 0; h < 8; h++) {
        __syncthreads();
        for (int i = threadIdx.x; i < 4096; i += 256) {
            int r = i >> 6, e = i & 63;
            int gr = rb + r;
            int b = gr >> 13, q = (gr >> 3) & 1023, m = gr & 7;
            sA[r][e] = g_out[(size_t)((b*8 + h)*1024 + q)*512 + m*64 + e];
            sB[r][e] = Wo[r*512 + h*64 + e];
        }
        __syncthreads();
        #pragma unroll
        for (int k = 0; k < 64; k++) {
            float a[4], bb[4];
            #pragma unroll
            for (int i = 0; i < 4; i++) a[i]  = sA[ty*4 + i][k];
            #pragma unroll
            for (int j = 0; j < 4; j++) bb[j] = sB[tx*4 + j][k];
            #pragma unroll
            for (int i = 0; i < 4; i++)
                #pragma unroll
                for (int j = 0; j < 4; j++)
                    acc[i][j] = fmaf(a[i], bb[j], acc[i][j]);
        }
    }
    #pragma unroll
    for (int i = 0; i < 4; i++)
        #pragma unroll
        for (int j = 0; j < 4; j++)
            out_atoms[(size_t)(rb + ty*4 + i)*64 + tx*4 + j] = acc[i][j];
}

// ---------------- K8: log-weight update ----------------
__global__ __launch_bounds__(64) void k_lw(const float* __restrict__ Ww,
                                           const float* __restrict__ qlw,
                                           const float* __restrict__ out_atoms,
                                           float* __restrict__ out2) {
    __shared__ float mean[64];
    int bq = blockIdx.x;
    int t = threadIdx.x;
    float s = 0.f;
    #pragma unroll
    for (int m = 0; m < 8; m++)
        s += out_atoms[(size_t)(bq*8 + m)*64 + t];
    mean[t] = s * 0.125f;
    __syncthreads();
    if (t < 8) {
        float acc = 0.f;
        #pragma unroll
        for (int d = 0; d < 64; d++)
            acc = fmaf(mean[d], Ww[t*64 + d], acc);
        out2[bq*8 + t] = qlw[bq*8 + t] + acc;
    }
}

// ---------------- launch ----------------
extern "C" void kernel_launch(void* const* d_in, const int* in_sizes, int n_in,
                              void* d_out, int out_size) {
    const float* q_atoms   = (const float*)d_in[0];
    const float* q_weights = (const float*)d_in[1];
    const float* q_logw    = (const float*)d_in[2];
    const float* k_atoms   = (const float*)d_in[3];
    const float* k_weights = (const float*)d_in[4];
    const float* v_atoms   = (const float*)d_in[5];
    const float* Wq        = (const float*)d_in[6];
    const float* Wk        = (const float*)d_in[7];
    const float* Wv        = (const float*)d_in[8];
    const float* Wo        = (const float*)d_in[9];
    const float* Ww        = (const float*)d_in[10];
    const float* log_bw    = (const float*)d_in[11];
    const float* log_temp  = (const float*)d_in[12];
    const float* rff_base  = (const float*)d_in[13];

    float* out_atoms = (float*)d_out;
    float* out_lw    = (float*)d_out + (size_t)B_*SQ_*M_*D_;

    k_combine<<<H_, 256>>>(Wq, Wk, rff_base, log_bw);
    k_rff<<<dim3(SQ_/16,  BH_), 256>>>(q_atoms, q_weights, 1);
    k_rff<<<dim3(SKV_/16, BH_), 256>>>(k_atoms, k_weights, 0);
    k_va<<<dim3(8, 512), 256>>>(v_atoms, Wv);
    k_mma<true><<<dim3(8, 8, BH_), 256>>>(log_temp);     // scores: N=1024
    k_softmax<<<BH_*SQ_, 256>>>();
    k_mma<false><<<dim3(4, 8, BH_), 256>>>(log_temp);    // attn @ va: N=512
    k_oproj<<<512, 256>>>(Wo, out_atoms);
    k_lw<<<B_*SQ_, 64>>>(Ww, q_logw, out_atoms, out_lw);
}

// round 5
// speedup vs baseline: 2.3672x; 1.2345x over previous
#include <cuda_runtime.h>
#include <cuda_fp16.h>
#include <cstdint>
#include <math.h>

#define B_   4
#define SQ_  1024
#define SKV_ 1024
#define M_   8
#define D_   64
#define H_   8
#define F_   64
#define BH_  (B_*H_)

// ---------------- scratch (device globals; no allocation) ----------------
__device__ float  g_Wqf[H_*D_*F_];
__device__ float  g_Wkf[H_*D_*F_];
__device__ __half g_qrff[(size_t)BH_*SQ_*2*F_];      // [bh][q][128]
__device__ __half g_krff[(size_t)BH_*SKV_*2*F_];     // [bh][k][128]
__device__ __half g_va  [(size_t)BH_*SKV_*512];      // [bh][s][n]  (n-contiguous)
__device__ float  g_scores[(size_t)BH_*SQ_*SKV_];    // fp32 logits
__device__ __half g_attn[(size_t)BH_*SQ_*SKV_];      // half attn
__device__ float  g_out [(size_t)BH_*SQ_*M_*D_];     // [bh][q][m*64+e]

__device__ __forceinline__ uint32_t s2u(const void* p) {
    uint32_t a;
    asm("{ .reg .u64 t; cvta.to.shared.u64 t, %1; cvt.u32.u64 %0, t; }" : "=r"(a) : "l"(p));
    return a;
}

// ---------------- K1: combined projection-RFF matrices ----------------
__global__ __launch_bounds__(256) void k_combine(const float* __restrict__ Wq,
                                                 const float* __restrict__ Wk,
                                                 const float* __restrict__ base,
                                                 const float* __restrict__ log_bw) {
    __shared__ float sWq[64*64], sWk[64*64], sB[64*64];
    int h = blockIdx.x;
    float inv = expf(-log_bw[h]);
    for (int i = threadIdx.x; i < 4096; i += 256) {
        sWq[i] = Wq[h*4096 + i];
        sWk[i] = Wk[h*4096 + i];
        sB[i]  = base[h*4096 + i] * inv;
    }
    __syncthreads();
    for (int idx = threadIdx.x; idx < 4096; idx += 256) {
        int d = idx >> 6, f = idx & 63;
        float aq = 0.f, ak = 0.f;
        #pragma unroll
        for (int e = 0; e < 64; e++) {
            float bf = sB[e*64 + f];
            aq = fmaf(sWq[e*64 + d], bf, aq);
            ak = fmaf(sWk[e*64 + d], bf, ak);
        }
        g_Wqf[h*4096 + d*64 + f] = aq;
        g_Wkf[h*4096 + d*64 + f] = ak;
    }
}

// ---------------- K2: fused projection + RFF encode (half out) ----------------
// 256 threads = 4 s-lanes x 64 f. W cached transposed [f][d] so each thread
// keeps its W d-quad in registers, reused across all 8 m.
__global__ __launch_bounds__(256) void k_rff(const float* __restrict__ atoms,
                                             const float* __restrict__ weights,
                                             int is_q) {
    __shared__ float sWT[64*68];            // [f][d], pad 68
    __shared__ __align__(16) float sAt[4][8][64];
    __shared__ float sw[4][8];
    int bh = blockIdx.y;
    int b = bh >> 3, h = bh & 7;
    const float* Wf = is_q ? g_Wqf : g_Wkf;
    __half* dstbase = (is_q ? g_qrff : g_krff);
    for (int i = threadIdx.x; i < 4096; i += 256) {
        int d = i >> 6, f = i & 63;
        sWT[f*68 + d] = Wf[h*4096 + i];
    }
    int s0 = blockIdx.x * 16;
    int f  = threadIdx.x & 63;
    int sl = threadIdx.x >> 6;
    for (int ss = 0; ss < 16; ss += 4) {
        __syncthreads();
        for (int i = threadIdx.x; i < 2048; i += 256) {
            int si = i >> 9;
            int md = i & 511;
            sAt[si][md >> 6][md & 63] =
                atoms[(size_t)(b*1024 + s0 + ss + si)*512 + md];
        }
        if (threadIdx.x < 32) {
            int si = threadIdx.x >> 3, m = threadIdx.x & 7;
            sw[si][m] = weights[(b*1024 + s0 + ss + si)*8 + m];
        }
        __syncthreads();
        float p[8];
        #pragma unroll
        for (int m = 0; m < 8; m++) p[m] = 0.f;
        #pragma unroll
        for (int dq = 0; dq < 64; dq += 4) {
            float4 wv = *(const float4*)&sWT[f*68 + dq];
            #pragma unroll
            for (int m = 0; m < 8; m++) {
                float4 av = *(const float4*)&sAt[sl][m][dq];
                p[m] = fmaf(av.x, wv.x, p[m]);
                p[m] = fmaf(av.y, wv.y, p[m]);
                p[m] = fmaf(av.z, wv.z, p[m]);
                p[m] = fmaf(av.w, wv.w, p[m]);
            }
        }
        float ac = 0.f, asn = 0.f;
        #pragma unroll
        for (int m = 0; m < 8; m++) {
            float sv, cv;
            __sincosf(p[m], &sv, &cv);
            float w = sw[sl][m];
            ac  = fmaf(w, cv, ac);
            asn = fmaf(w, sv, asn);
        }
        int s = s0 + ss + sl;
        __half* dst = dstbase + ((size_t)bh*1024 + s)*128;
        dst[f]      = __float2half(ac  * 0.125f);
        dst[64 + f] = __float2half(asn * 0.125f);
    }
}

// ---------------- K3: va projection -> half g_va[bh][s][n], coalesced ----------------
__global__ __launch_bounds__(256) void k_va(const float* __restrict__ v_atoms,
                                            const float* __restrict__ Wv) {
    __shared__ float sA[64][65];
    __shared__ float sB[64][65];
    __shared__ __align__(16) __half sO[8][512];
    int rb = blockIdx.y * 64, cb = blockIdx.x * 64;
    for (int i = threadIdx.x; i < 4096; i += 256) {
        int r = i >> 6, d = i & 63;
        sA[r][d] = v_atoms[(size_t)(rb + r)*64 + d];
        sB[r][d] = Wv[(cb + r)*64 + d];
    }
    __syncthreads();
    int tx = threadIdx.x & 15, ty = threadIdx.x >> 4;
    float acc[4][4] = {};
    #pragma unroll
    for (int k = 0; k < 64; k++) {
        float a[4], bb[4];
        #pragma unroll
        for (int i = 0; i < 4; i++) a[i]  = sA[ty*4 + i][k];
        #pragma unroll
        for (int j = 0; j < 4; j++) bb[j] = sB[tx*4 + j][k];
        #pragma unroll
        for (int i = 0; i < 4; i++)
            #pragma unroll
            for (int j = 0; j < 4; j++)
                acc[i][j] = fmaf(a[i], bb[j], acc[i][j]);
    }
    // stage into [s_local][m*64+e]
    #pragma unroll
    for (int i = 0; i < 4; i++) {
        int rl = ty*4 + i;           // 0..63: s_l = rl>>3, m = rl&7
        int s_l = rl >> 3, m = rl & 7;
        #pragma unroll
        for (int j = 0; j < 4; j++)
            sO[s_l][m*64 + tx*4 + j] = __float2half(acc[i][j]);
    }
    __syncthreads();
    int b = rb >> 13, s0 = (rb >> 3) & 1023;
    int h = cb >> 6;
    int bh = b*8 + h;
    #pragma unroll
    for (int i = 0; i < 2; i++) {
        int idx = threadIdx.x + i*256;     // 0..511
        int row = idx >> 6, c = idx & 63;
        *(uint4*)&g_va[((size_t)bh*1024 + s0 + row)*512 + c*8] =
            *(const uint4*)&sO[row][c*8];
    }
}

// ---------------- K4/K6: mma.sync GEMM ----------------
// SC=true : scores = qrff @ krff^T  (both K-contiguous, non-trans B)
// SC=false: out = attn @ va         (va is [k][n], trans-B via ldmatrix.trans)
template<bool SC>
__global__ __launch_bounds__(256) void k_mma(const float* __restrict__ log_temp) {
    constexpr int NCHUNK = SC ? 4 : 32;                 // K = NCHUNK*32
    constexpr int ASTR   = SC ? 128 : 1024;
    constexpr int CSTR   = SC ? 1024 : 512;
    const __half* Ag = SC ? g_qrff : g_attn;
    const __half* Bg = SC ? g_krff : g_va;
    float*        Cg = SC ? g_scores : g_out;

    __shared__ __align__(16) __half sA[2][128][40];
    __shared__ __align__(16) __half sBraw[2][128][40];   // SC view: [n][k]
    __half (*sB2)[32][136] = (__half (*)[32][136])sBraw; // !SC view: [k][n]

    int tid = threadIdx.x, wid = tid >> 5, lid = tid & 31;
    int bh = blockIdx.z;
    int qb = blockIdx.y * 128, nb = blockIdx.x * 128;
    const __half* Ab = Ag + (size_t)bh*1024*ASTR + (size_t)qb*ASTR;

    int warp_m = (wid & 3) * 32;
    int warp_n = (wid >> 2) * 64;
    float acc[2][8][4] = {};

    auto load = [&](int st, int kc) {
        #pragma unroll
        for (int i = 0; i < 2; i++) {
            int id = tid + i*256;              // 0..511
            int row = id >> 2, c = id & 3;
            uint32_t d = s2u(&sA[st][row][c*8]);
            asm volatile("cp.async.cg.shared.global [%0], [%1], 16;"
                         :: "r"(d), "l"(Ab + (size_t)row*ASTR + kc + c*8));
        }
        if constexpr (SC) {
            const __half* Bb = Bg + (size_t)bh*1024*128 + (size_t)nb*128;
            #pragma unroll
            for (int i = 0; i < 2; i++) {
                int id = tid + i*256;
                int row = id >> 2, c = id & 3;
                uint32_t d = s2u(&sBraw[st][row][c*8]);
                asm volatile("cp.async.cg.shared.global [%0], [%1], 16;"
                             :: "r"(d), "l"(Bb + (size_t)row*128 + kc + c*8));
            }
        } else {
            const __half* Bb = Bg + (size_t)bh*1024*512 + nb;
            #pragma unroll
            for (int i = 0; i < 2; i++) {
                int id = tid + i*256;              // 0..511
                int row = id >> 4, c = id & 15;    // 32 k-rows x 16 chunks
                uint32_t d = s2u(&sB2[st][row][c*8]);
                asm volatile("cp.async.cg.shared.global [%0], [%1], 16;"
                             :: "r"(d), "l"(Bb + (size_t)(kc + row)*512 + c*8));
            }
        }
        asm volatile("cp.async.commit_group;" ::: "memory");
    };

    load(0, 0);
    load(1, 32);

    for (int c = 0; c < NCHUNK; c++) {
        int st = c & 1;
        if (c + 2 < NCHUNK) asm volatile("cp.async.wait_group 1;" ::: "memory");
        else                asm volatile("cp.async.wait_group 0;" ::: "memory");
        __syncthreads();

        #pragma unroll
        for (int kk = 0; kk < 32; kk += 16) {
            uint32_t af[2][4];
            #pragma unroll
            for (int mi = 0; mi < 2; mi++) {
                uint32_t addr = s2u(&sA[st][warp_m + mi*16 + (lid & 15)][kk + ((lid >> 4) << 3)]);
                asm volatile("ldmatrix.sync.aligned.m8n8.x4.shared.b16 {%0,%1,%2,%3}, [%4];"
                    : "=r"(af[mi][0]), "=r"(af[mi][1]), "=r"(af[mi][2]), "=r"(af[mi][3])
                    : "r"(addr));
            }
            uint32_t bf[8][2];
            #pragma unroll
            for (int nj = 0; nj < 4; nj++) {
                uint32_t r0, r1, r2, r3;
                if constexpr (SC) {
                    int n = warp_n + nj*16 + ((lid >> 4) << 3) + (lid & 7);
                    int k = kk + (((lid >> 3) & 1) << 3);
                    uint32_t addr = s2u(&sBraw[st][n][k]);
                    asm volatile("ldmatrix.sync.aligned.m8n8.x4.shared.b16 {%0,%1,%2,%3}, [%4];"
                        : "=r"(r0), "=r"(r1), "=r"(r2), "=r"(r3) : "r"(addr));
                    bf[nj*2][0]   = r0; bf[nj*2][1]   = r1;
                    bf[nj*2+1][0] = r2; bf[nj*2+1][1] = r3;
                } else {
                    // trans: m0=(kk,n0) m1=(kk+8,n0) m2=(kk,n0+8) m3=(kk+8,n0+8)
                    int krow = kk + (lid & 7) + (((lid >> 3) & 1) << 3);
                    int ncol = warp_n + nj*16 + ((lid >> 4) << 3);
                    uint32_t addr = s2u(&sB2[st][krow][ncol]);
                    asm volatile("ldmatrix.sync.aligned.m8n8.x4.trans.shared.b16 {%0,%1,%2,%3}, [%4];"
                        : "=r"(r0), "=r"(r1), "=r"(r2), "=r"(r3) : "r"(addr));
                    bf[nj*2][0]   = r0; bf[nj*2][1]   = r1;   // n0..n0+7 : k lo, k hi
                    bf[nj*2+1][0] = r2; bf[nj*2+1][1] = r3;   // n0+8..n0+15
                }
            }
            #pragma unroll
            for (int mi = 0; mi < 2; mi++)
                #pragma unroll
                for (int ni = 0; ni < 8; ni++)
                    asm volatile("mma.sync.aligned.m16n8k16.row.col.f32.f16.f16.f32 "
                        "{%0,%1,%2,%3}, {%4,%5,%6,%7}, {%8,%9}, {%0,%1,%2,%3};"
                        : "+f"(acc[mi][ni][0]), "+f"(acc[mi][ni][1]),
                          "+f"(acc[mi][ni][2]), "+f"(acc[mi][ni][3])
                        : "r"(af[mi][0]), "r"(af[mi][1]), "r"(af[mi][2]), "r"(af[mi][3]),
                          "r"(bf[ni][0]), "r"(bf[ni][1]));
        }
        __syncthreads();
        if (c + 2 < NCHUNK) load(st, (c + 2)*32);
    }

    float scale = SC ? __expf(log_temp[bh & 7]) : 1.f;
    #pragma unroll
    for (int mi = 0; mi < 2; mi++) {
        #pragma unroll
        for (int ni = 0; ni < 8; ni++) {
            int row = qb + warp_m + mi*16 + (lid >> 2);
            int col = nb + warp_n + ni*8 + (lid & 3)*2;
            float* Cp = Cg + (size_t)bh*1024*CSTR + (size_t)row*CSTR + col;
            Cp[0]                  = acc[mi][ni][0] * scale;
            Cp[1]                  = acc[mi][ni][1] * scale;
            Cp[(size_t)CSTR*8]     = acc[mi][ni][2] * scale;
            Cp[(size_t)CSTR*8 + 1] = acc[mi][ni][3] * scale;
        }
    }
}

// ---------------- K5: row softmax (fp32 in, half out) ----------------
__global__ __launch_bounds__(256) void k_softmax() {
    __shared__ float red[8];
    size_t row = blockIdx.x;
    const float4* p = (const float4*)(g_scores + row*1024);
    int t = threadIdx.x;
    float4 v = p[t];
    float mx = fmaxf(fmaxf(v.x, v.y), fmaxf(v.z, v.w));
    #pragma unroll
    for (int o = 16; o; o >>= 1) mx = fmaxf(mx, __shfl_xor_sync(~0u, mx, o));
    if ((t & 31) == 0) red[t >> 5] = mx;
    __syncthreads();
    float rm = red[0];
    #pragma unroll
    for (int i = 1; i < 8; i++) rm = fmaxf(rm, red[i]);
    v.x = __expf(v.x - rm); v.y = __expf(v.y - rm);
    v.z = __expf(v.z - rm); v.w = __expf(v.w - rm);
    float s = v.x + v.y + v.z + v.w;
    #pragma unroll
    for (int o = 16; o; o >>= 1) s += __shfl_xor_sync(~0u, s, o);
    __syncthreads();
    if ((t & 31) == 0) red[t >> 5] = s;
    __syncthreads();
    float tot = 0.f;
    #pragma unroll
    for (int i = 0; i < 8; i++) tot += red[i];
    float inv = 1.0f / tot;
    __half2* o2 = (__half2*)(g_attn + row*1024);
    o2[2*t]     = __floats2half2_rn(v.x * inv, v.y * inv);
    o2[2*t + 1] = __floats2half2_rn(v.z * inv, v.w * inv);
}

// ---------------- K7: output projection ----------------
__global__ __launch_bounds__(256) void k_oproj(const float* __restrict__ Wo,
                                               float* __restrict__ out_atoms) {
    __shared__ float sA[64][65];
    __shared__ float sB[64][65];
    int rb = blockIdx.x * 64;
    int tx = threadIdx.x & 15, ty = threadIdx.x >> 4;
    float acc[4][4] = {};
    for (int h = 0; h < 8; h++) {
        __syncthreads();
        for (int i = threadIdx.x; i < 4096; i += 256) {
            int r = i >> 6, e = i & 63;
            int gr = rb + r;
            int b = gr >> 13, q = (gr >> 3) & 1023, m = gr & 7;
            sA[r][e] = g_out[(size_t)((b*8 + h)*1024 + q)*512 + m*64 + e];
            sB[r][e] = Wo[r*512 + h*64 + e];
        }
        __syncthreads();
        #pragma unroll
        for (int k = 0; k < 64; k++) {
            float a[4], bb[4];
            #pragma unroll
            for (int i = 0; i < 4; i++) a[i]  = sA[ty*4 + i][k];
            #pragma unroll
            for (int j = 0; j < 4; j++) bb[j] = sB[tx*4 + j][k];
            #pragma unroll
            for (int i = 0; i < 4; i++)
                #pragma unroll
                for (int j = 0; j < 4; j++)
                    acc[i][j] = fmaf(a[i], bb[j], acc[i][j]);
        }
    }
    #pragma unroll
    for (int i = 0; i < 4; i++)
        #pragma unroll
        for (int j = 0; j < 4; j++)
            out_atoms[(size_t)(rb + ty*4 + i)*64 + tx*4 + j] = acc[i][j];
}

// ---------------- K8: log-weight update ----------------
__global__ __launch_bounds__(64) void k_lw(const float* __restrict__ Ww,
                                           const float* __restrict__ qlw,
                                           const float* __restrict__ out_atoms,
                                           float* __restrict__ out2) {
    __shared__ float mean[64];
    int bq = blockIdx.x;
    int t = threadIdx.x;
    float s = 0.f;
    #pragma unroll
    for (int m = 0; m < 8; m++)
        s += out_atoms[(size_t)(bq*8 + m)*64 + t];
    mean[t] = s * 0.125f;
    __syncthreads();
    if (t < 8) {
        float acc = 0.f;
        #pragma unroll
        for (int d = 0; d < 64; d++)
            acc = fmaf(mean[d], Ww[t*64 + d], acc);
        out2[bq*8 + t] = qlw[bq*8 + t] + acc;
    }
}

// ---------------- launch ----------------
extern "C" void kernel_launch(void* const* d_in, const int* in_sizes, int n_in,
                              void* d_out, int out_size) {
    const float* q_atoms   = (const float*)d_in[0];
    const float* q_weights = (const float*)d_in[1];
    const float* q_logw    = (const float*)d_in[2];
    const float* k_atoms   = (const float*)d_in[3];
    const float* k_weights = (const float*)d_in[4];
    const float* v_atoms   = (const float*)d_in[5];
    const float* Wq        = (const float*)d_in[6];
    const float* Wk        = (const float*)d_in[7];
    const float* Wv        = (const float*)d_in[8];
    const float* Wo        = (const float*)d_in[9];
    const float* Ww        = (const float*)d_in[10];
    const float* log_bw    = (const float*)d_in[11];
    const float* log_temp  = (const float*)d_in[12];
    const float* rff_base  = (const float*)d_in[13];

    float* out_atoms = (float*)d_out;
    float* out_lw    = (float*)d_out + (size_t)B_*SQ_*M_*D_;

    k_combine<<<H_, 256>>>(Wq, Wk, rff_base, log_bw);
    k_rff<<<dim3(SQ_/16,  BH_), 256>>>(q_atoms, q_weights, 1);
    k_rff<<<dim3(SKV_/16, BH_), 256>>>(k_atoms, k_weights, 0);
    k_va<<<dim3(8, 512), 256>>>(v_atoms, Wv);
    k_mma<true><<<dim3(8, 8, BH_), 256>>>(log_temp);     // scores
    k_softmax<<<BH_*SQ_, 256>>>();
    k_mma<false><<<dim3(4, 8, BH_), 256>>>(log_temp);    // attn @ va
    k_oproj<<<512, 256>>>(Wo, out_atoms);
    k_lw<<<B_*SQ_, 64>>>(Ww, q_logw, out_atoms, out_lw);
}

// round 6
// speedup vs baseline: 2.4827x; 1.0488x over previous
#include <cuda_runtime.h>
#include <cuda_fp16.h>
#include <cstdint>
#include <math.h>

#define B_   4
#define SQ_  1024
#define SKV_ 1024
#define M_   8
#define D_   64
#define H_   8
#define F_   64
#define BH_  (B_*H_)

// ---------------- scratch (device globals; no allocation) ----------------
__device__ float  g_Wqf[H_*D_*F_];
__device__ float  g_Wkf[H_*D_*F_];
__device__ __half g_qrff[(size_t)BH_*SQ_*2*F_];      // [bh][q][128]
__device__ __half g_krff[(size_t)BH_*SKV_*2*F_];     // [bh][k][128]
__device__ __half g_va  [(size_t)BH_*SKV_*512];      // [bh][s][n]  (n-contiguous)
__device__ float  g_scores[(size_t)BH_*SQ_*SKV_];    // fp32 logits
__device__ __half g_attn[(size_t)BH_*SQ_*SKV_];      // half attn
__device__ float  g_out [(size_t)BH_*SQ_*M_*D_];     // [bh][q][m*64+e]

__device__ __forceinline__ uint32_t s2u(const void* p) {
    uint32_t a;
    asm("{ .reg .u64 t; cvta.to.shared.u64 t, %1; cvt.u32.u64 %0, t; }" : "=r"(a) : "l"(p));
    return a;
}

// ---------------- K1: combined projection-RFF matrices ----------------
__global__ __launch_bounds__(256) void k_combine(const float* __restrict__ Wq,
                                                 const float* __restrict__ Wk,
                                                 const float* __restrict__ base,
                                                 const float* __restrict__ log_bw) {
    __shared__ float sWq[64*64], sWk[64*64], sB[64*64];
    int h = blockIdx.x;
    float inv = expf(-log_bw[h]);
    for (int i = threadIdx.x; i < 4096; i += 256) {
        sWq[i] = Wq[h*4096 + i];
        sWk[i] = Wk[h*4096 + i];
        sB[i]  = base[h*4096 + i] * inv;
    }
    __syncthreads();
    for (int idx = threadIdx.x; idx < 4096; idx += 256) {
        int d = idx >> 6, f = idx & 63;
        float aq = 0.f, ak = 0.f;
        #pragma unroll
        for (int e = 0; e < 64; e++) {
            float bf = sB[e*64 + f];
            aq = fmaf(sWq[e*64 + d], bf, aq);
            ak = fmaf(sWk[e*64 + d], bf, ak);
        }
        g_Wqf[h*4096 + d*64 + f] = aq;
        g_Wkf[h*4096 + d*64 + f] = ak;
    }
}

// ---------------- K2: fused projection + RFF encode (half out) ----------------
__global__ __launch_bounds__(256) void k_rff(const float* __restrict__ atoms,
                                             const float* __restrict__ weights,
                                             int is_q) {
    __shared__ float sWT[64*68];            // [f][d], pad 68
    __shared__ __align__(16) float sAt[4][8][64];
    __shared__ float sw[4][8];
    int bh = blockIdx.y;
    int b = bh >> 3, h = bh & 7;
    const float* Wf = is_q ? g_Wqf : g_Wkf;
    __half* dstbase = (is_q ? g_qrff : g_krff);
    for (int i = threadIdx.x; i < 4096; i += 256) {
        int d = i >> 6, f = i & 63;
        sWT[f*68 + d] = Wf[h*4096 + i];
    }
    int s0 = blockIdx.x * 16;
    int f  = threadIdx.x & 63;
    int sl = threadIdx.x >> 6;
    for (int ss = 0; ss < 16; ss += 4) {
        __syncthreads();
        for (int i = threadIdx.x; i < 2048; i += 256) {
            int si = i >> 9;
            int md = i & 511;
            sAt[si][md >> 6][md & 63] =
                atoms[(size_t)(b*1024 + s0 + ss + si)*512 + md];
        }
        if (threadIdx.x < 32) {
            int si = threadIdx.x >> 3, m = threadIdx.x & 7;
            sw[si][m] = weights[(b*1024 + s0 + ss + si)*8 + m];
        }
        __syncthreads();
        float p[8];
        #pragma unroll
        for (int m = 0; m < 8; m++) p[m] = 0.f;
        #pragma unroll
        for (int dq = 0; dq < 64; dq += 4) {
            float4 wv = *(const float4*)&sWT[f*68 + dq];
            #pragma unroll
            for (int m = 0; m < 8; m++) {
                float4 av = *(const float4*)&sAt[sl][m][dq];
                p[m] = fmaf(av.x, wv.x, p[m]);
                p[m] = fmaf(av.y, wv.y, p[m]);
                p[m] = fmaf(av.z, wv.z, p[m]);
                p[m] = fmaf(av.w, wv.w, p[m]);
            }
        }
        float ac = 0.f, asn = 0.f;
        #pragma unroll
        for (int m = 0; m < 8; m++) {
            float sv, cv;
            __sincosf(p[m], &sv, &cv);
            float w = sw[sl][m];
            ac  = fmaf(w, cv, ac);
            asn = fmaf(w, sv, asn);
        }
        int s = s0 + ss + sl;
        __half* dst = dstbase + ((size_t)bh*1024 + s)*128;
        dst[f]      = __float2half(ac  * 0.125f);
        dst[64 + f] = __float2half(asn * 0.125f);
    }
}

// ---------------- K3: va projection, 128x128 tile, 8x8 microtile ----------------
// rows r = (b*1024+s)*8+m over 32768; cols c = h*64+e over 512; K = 64 (d)
// out g_va[((b*8+h)*1024+s)*512 + m*64+e]
__global__ __launch_bounds__(256) void k_va(const float* __restrict__ v_atoms,
                                            const float* __restrict__ Wv) {
    __shared__ __align__(16) char sraw[32768];
    float (*sa)[16][128] = (float (*)[16][128])sraw;            // [st][k][row]
    float (*sb)[16][128] = (float (*)[16][128])(sraw + 16384);  // [st][k][col]
    __half (*so)[2][512] = (__half (*)[2][512])sraw;            // [s16][h2][512]

    int rb = blockIdx.y * 128, cb = blockIdx.x * 128;
    int tid = threadIdx.x;
    int tx = tid & 15, ty = tid >> 4;
    float acc[8][8] = {};

    auto load = [&](int st, int kc) {
        #pragma unroll
        for (int i = 0; i < 2; i++) {
            int id = tid + i*256;            // 0..511
            int r = id >> 2, c = (id & 3)*4;
            float4 av = *(const float4*)&v_atoms[(size_t)(rb + r)*64 + kc + c];
            sa[st][c+0][r] = av.x; sa[st][c+1][r] = av.y;
            sa[st][c+2][r] = av.z; sa[st][c+3][r] = av.w;
            float4 bv = *(const float4*)&Wv[(size_t)(cb + r)*64 + kc + c];
            sb[st][c+0][r] = bv.x; sb[st][c+1][r] = bv.y;
            sb[st][c+2][r] = bv.z; sb[st][c+3][r] = bv.w;
        }
    };

    load(0, 0);
    #pragma unroll
    for (int ch = 0; ch < 4; ch++) {
        __syncthreads();
        if (ch < 3) load(ch + 1 & 1, (ch + 1)*16);   // note: (ch+1)&1
        int st = ch & 1;
        // need data of chunk ch ready: it was loaded before the barrier above
        #pragma unroll
        for (int k = 0; k < 16; k++) {
            float a[8], bv[8];
            *(float4*)&a[0]  = *(const float4*)&sa[st][k][ty*8];
            *(float4*)&a[4]  = *(const float4*)&sa[st][k][ty*8 + 4];
            *(float4*)&bv[0] = *(const float4*)&sb[st][k][tx*8];
            *(float4*)&bv[4] = *(const float4*)&sb[st][k][tx*8 + 4];
            #pragma unroll
            for (int i = 0; i < 8; i++)
                #pragma unroll
                for (int j = 0; j < 8; j++)
                    acc[i][j] = fmaf(a[i], bv[j], acc[i][j]);
        }
    }
    __syncthreads();
    // stage into [s_l][h_l][m*64+e]
    #pragma unroll
    for (int i = 0; i < 8; i++) {
        int rl = ty*8 + i;
        int s_l = rl >> 3, m = rl & 7;
        __half hv[8];
        #pragma unroll
        for (int j = 0; j < 8; j++) hv[j] = __float2half(acc[i][j]);
        int h_l = (tx*8) >> 6, e0 = (tx*8) & 63;
        *(uint4*)&so[s_l][h_l][m*64 + e0] = *(const uint4*)hv;
    }
    __syncthreads();
    int b = rb >> 13, s0 = (rb >> 3) & 1023;
    int h0 = cb >> 6;
    #pragma unroll
    for (int i = 0; i < 8; i++) {
        int idx = tid + i*256;               // 0..2047
        int row = idx >> 6, c = idx & 63;    // row: s_l*2+h_l
        int s_l = row >> 1, h_l = row & 1;
        *(uint4*)&g_va[((size_t)((b*8 + h0 + h_l)*1024) + s0 + s_l)*512 + c*8] =
            *(const uint4*)&so[s_l][h_l][c*8];
    }
}

// ---------------- K4/K6: mma.sync GEMM, 3-stage cp.async pipeline ----------------
// SC=true : scores = qrff @ krff^T  (B [n][k], non-trans ldmatrix)
// SC=false: out = attn @ va         (B [k][n], ldmatrix.trans)
#define MMA_SMEM 61440
template<bool SC>
__global__ __launch_bounds__(256) void k_mma(const float* __restrict__ log_temp) {
    constexpr int NCHUNK = SC ? 4 : 32;                 // K = NCHUNK*32
    constexpr int ASTR   = SC ? 128 : 1024;
    constexpr int CSTR   = SC ? 1024 : 512;
    const __half* Ag = SC ? g_qrff : g_attn;
    const __half* Bg = SC ? g_krff : g_va;
    float*        Cg = SC ? g_scores : g_out;

    extern __shared__ __align__(16) __half dsm[];
    // per-stage: A 128x40, B 5120 halves (SC: [128][40], !SC: [32][136])
    auto aPtr = [&](int st, int row, int col) -> __half* {
        return dsm + st*5120 + row*40 + col;
    };
    auto bPtr = [&](int st, int row, int col) -> __half* {
        return dsm + 15360 + st*5120 + (SC ? row*40 : row*136) + col;
    };

    int tid = threadIdx.x, wid = tid >> 5, lid = tid & 31;
    int bh = blockIdx.z;
    int qb = blockIdx.y * 128, nb = blockIdx.x * 128;
    const __half* Ab = Ag + (size_t)bh*1024*ASTR + (size_t)qb*ASTR;

    int warp_m = (wid & 3) * 32;
    int warp_n = (wid >> 2) * 64;
    float acc[2][8][4] = {};

    auto load = [&](int st, int kc) {
        #pragma unroll
        for (int i = 0; i < 2; i++) {
            int id = tid + i*256;              // 0..511
            int row = id >> 2, c = id & 3;
            uint32_t d = s2u(aPtr(st, row, c*8));
            asm volatile("cp.async.cg.shared.global [%0], [%1], 16;"
                         :: "r"(d), "l"(Ab + (size_t)row*ASTR + kc + c*8));
        }
        if constexpr (SC) {
            const __half* Bb = Bg + (size_t)bh*1024*128 + (size_t)nb*128;
            #pragma unroll
            for (int i = 0; i < 2; i++) {
                int id = tid + i*256;
                int row = id >> 2, c = id & 3;
                uint32_t d = s2u(bPtr(st, row, c*8));
                asm volatile("cp.async.cg.shared.global [%0], [%1], 16;"
                             :: "r"(d), "l"(Bb + (size_t)row*128 + kc + c*8));
            }
        } else {
            const __half* Bb = Bg + (size_t)bh*1024*512 + nb;
            #pragma unroll
            for (int i = 0; i < 2; i++) {
                int id = tid + i*256;              // 0..511
                int row = id >> 4, c = id & 15;    // 32 k-rows x 16 chunks
                uint32_t d = s2u(bPtr(st, row, c*8));
                asm volatile("cp.async.cg.shared.global [%0], [%1], 16;"
                             :: "r"(d), "l"(Bb + (size_t)(kc + row)*512 + c*8));
            }
        }
        asm volatile("cp.async.commit_group;" ::: "memory");
    };

    load(0, 0);
    load(1, 32);

    for (int c = 0; c < NCHUNK; c++) {
        int st = c % 3;
        if (c == NCHUNK - 1) asm volatile("cp.async.wait_group 0;" ::: "memory");
        else                 asm volatile("cp.async.wait_group 1;" ::: "memory");
        __syncthreads();
        if (c + 2 < NCHUNK) load((c + 2) % 3, (c + 2)*32);

        #pragma unroll
        for (int kk = 0; kk < 32; kk += 16) {
            uint32_t af[2][4];
            #pragma unroll
            for (int mi = 0; mi < 2; mi++) {
                uint32_t addr = s2u(aPtr(st, warp_m + mi*16 + (lid & 15), kk + ((lid >> 4) << 3)));
                asm volatile("ldmatrix.sync.aligned.m8n8.x4.shared.b16 {%0,%1,%2,%3}, [%4];"
                    : "=r"(af[mi][0]), "=r"(af[mi][1]), "=r"(af[mi][2]), "=r"(af[mi][3])
                    : "r"(addr));
            }
            uint32_t bf[8][2];
            #pragma unroll
            for (int nj = 0; nj < 4; nj++) {
                uint32_t r0, r1, r2, r3;
                if constexpr (SC) {
                    int n = warp_n + nj*16 + ((lid >> 4) << 3) + (lid & 7);
                    int k = kk + (((lid >> 3) & 1) << 3);
                    uint32_t addr = s2u(bPtr(st, n, k));
                    asm volatile("ldmatrix.sync.aligned.m8n8.x4.shared.b16 {%0,%1,%2,%3}, [%4];"
                        : "=r"(r0), "=r"(r1), "=r"(r2), "=r"(r3) : "r"(addr));
                } else {
                    int krow = kk + (lid & 7) + (((lid >> 3) & 1) << 3);
                    int ncol = warp_n + nj*16 + ((lid >> 4) << 3);
                    uint32_t addr = s2u(bPtr(st, krow, ncol));
                    asm volatile("ldmatrix.sync.aligned.m8n8.x4.trans.shared.b16 {%0,%1,%2,%3}, [%4];"
                        : "=r"(r0), "=r"(r1), "=r"(r2), "=r"(r3) : "r"(addr));
                }
                bf[nj*2][0]   = r0; bf[nj*2][1]   = r1;
                bf[nj*2+1][0] = r2; bf[nj*2+1][1] = r3;
            }
            #pragma unroll
            for (int mi = 0; mi < 2; mi++)
                #pragma unroll
                for (int ni = 0; ni < 8; ni++)
                    asm volatile("mma.sync.aligned.m16n8k16.row.col.f32.f16.f16.f32 "
                        "{%0,%1,%2,%3}, {%4,%5,%6,%7}, {%8,%9}, {%0,%1,%2,%3};"
                        : "+f"(acc[mi][ni][0]), "+f"(acc[mi][ni][1]),
                          "+f"(acc[mi][ni][2]), "+f"(acc[mi][ni][3])
                        : "r"(af[mi][0]), "r"(af[mi][1]), "r"(af[mi][2]), "r"(af[mi][3]),
                          "r"(bf[ni][0]), "r"(bf[ni][1]));
        }
        __syncthreads();
    }

    float scale = SC ? __expf(log_temp[bh & 7]) : 1.f;
    #pragma unroll
    for (int mi = 0; mi < 2; mi++) {
        #pragma unroll
        for (int ni = 0; ni < 8; ni++) {
            int row = qb + warp_m + mi*16 + (lid >> 2);
            int col = nb + warp_n + ni*8 + (lid & 3)*2;
            float* Cp = Cg + (size_t)bh*1024*CSTR + (size_t)row*CSTR + col;
            Cp[0]                  = acc[mi][ni][0] * scale;
            Cp[1]                  = acc[mi][ni][1] * scale;
            Cp[(size_t)CSTR*8]     = acc[mi][ni][2] * scale;
            Cp[(size_t)CSTR*8 + 1] = acc[mi][ni][3] * scale;
        }
    }
}

// ---------------- K5: row softmax (fp32 in, half out) ----------------
__global__ __launch_bounds__(256) void k_softmax() {
    __shared__ float red[8];
    size_t row = blockIdx.x;
    const float4* p = (const float4*)(g_scores + row*1024);
    int t = threadIdx.x;
    float4 v = p[t];
    float mx = fmaxf(fmaxf(v.x, v.y), fmaxf(v.z, v.w));
    #pragma unroll
    for (int o = 16; o; o >>= 1) mx = fmaxf(mx, __shfl_xor_sync(~0u, mx, o));
    if ((t & 31) == 0) red[t >> 5] = mx;
    __syncthreads();
    float rm = red[0];
    #pragma unroll
    for (int i = 1; i < 8; i++) rm = fmaxf(rm, red[i]);
    v.x = __expf(v.x - rm); v.y = __expf(v.y - rm);
    v.z = __expf(v.z - rm); v.w = __expf(v.w - rm);
    float s = v.x + v.y + v.z + v.w;
    #pragma unroll
    for (int o = 16; o; o >>= 1) s += __shfl_xor_sync(~0u, s, o);
    __syncthreads();
    if ((t & 31) == 0) red[t >> 5] = s;
    __syncthreads();
    float tot = 0.f;
    #pragma unroll
    for (int i = 0; i < 8; i++) tot += red[i];
    float inv = 1.0f / tot;
    __half2* o2 = (__half2*)(g_attn + row*1024);
    o2[2*t]     = __floats2half2_rn(v.x * inv, v.y * inv);
    o2[2*t + 1] = __floats2half2_rn(v.z * inv, v.w * inv);
}

// ---------------- K7: output projection ----------------
__global__ __launch_bounds__(256) void k_oproj(const float* __restrict__ Wo,
                                               float* __restrict__ out_atoms) {
    __shared__ float sA[64][65];
    __shared__ float sB[64][65];
    int rb = blockIdx.x * 64;
    int tx = threadIdx.x & 15, ty = threadIdx.x >> 4;
    float acc[4][4] = {};
    for (int h = 0; h < 8; h++) {
        __syncthreads();
        for (int i = threadIdx.x; i < 4096; i += 256) {
            int r = i >> 6, e = i & 63;
            int gr = rb + r;
            int b = gr >> 13, q = (gr >> 3) & 1023, m = gr & 7;
            sA[r][e] = g_out[(size_t)((b*8 + h)*1024 + q)*512 + m*64 + e];
            sB[r][e] = Wo[r*512 + h*64 + e];
        }
        __syncthreads();
        #pragma unroll
        for (int k = 0; k < 64; k++) {
            float a[4], bb[4];
            #pragma unroll
            for (int i = 0; i < 4; i++) a[i]  = sA[ty*4 + i][k];
            #pragma unroll
            for (int j = 0; j < 4; j++) bb[j] = sB[tx*4 + j][k];
            #pragma unroll
            for (int i = 0; i < 4; i++)
                #pragma unroll
                for (int j = 0; j < 4; j++)
                    acc[i][j] = fmaf(a[i], bb[j], acc[i][j]);
        }
    }
    #pragma unroll
    for (int i = 0; i < 4; i++)
        #pragma unroll
        for (int j = 0; j < 4; j++)
            out_atoms[(size_t)(rb + ty*4 + i)*64 + tx*4 + j] = acc[i][j];
}

// ---------------- K8: log-weight update ----------------
__global__ __launch_bounds__(64) void k_lw(const float* __restrict__ Ww,
                                           const float* __restrict__ qlw,
                                           const float* __restrict__ out_atoms,
                                           float* __restrict__ out2) {
    __shared__ float mean[64];
    int bq = blockIdx.x;
    int t = threadIdx.x;
    float s = 0.f;
    #pragma unroll
    for (int m = 0; m < 8; m++)
        s += out_atoms[(size_t)(bq*8 + m)*64 + t];
    mean[t] = s * 0.125f;
    __syncthreads();
    if (t < 8) {
        float acc = 0.f;
        #pragma unroll
        for (int d = 0; d < 64; d++)
            acc = fmaf(mean[d], Ww[t*64 + d], acc);
        out2[bq*8 + t] = qlw[bq*8 + t] + acc;
    }
}

// ---------------- launch ----------------
extern "C" void kernel_launch(void* const* d_in, const int* in_sizes, int n_in,
                              void* d_out, int out_size) {
    const float* q_atoms   = (const float*)d_in[0];
    const float* q_weights = (const float*)d_in[1];
    const float* q_logw    = (const float*)d_in[2];
    const float* k_atoms   = (const float*)d_in[3];
    const float* k_weights = (const float*)d_in[4];
    const float* v_atoms   = (const float*)d_in[5];
    const float* Wq        = (const float*)d_in[6];
    const float* Wk        = (const float*)d_in[7];
    const float* Wv        = (const float*)d_in[8];
    const float* Wo        = (const float*)d_in[9];
    const float* Ww        = (const float*)d_in[10];
    const float* log_bw    = (const float*)d_in[11];
    const float* log_temp  = (const float*)d_in[12];
    const float* rff_base  = (const float*)d_in[13];

    float* out_atoms = (float*)d_out;
    float* out_lw    = (float*)d_out + (size_t)B_*SQ_*M_*D_;

    static int smem_set = 0;
    if (!smem_set) {
        cudaFuncSetAttribute(k_mma<true>,  cudaFuncAttributeMaxDynamicSharedMemorySize, MMA_SMEM);
        cudaFuncSetAttribute(k_mma<false>, cudaFuncAttributeMaxDynamicSharedMemorySize, MMA_SMEM);
        smem_set = 1;
    }

    k_combine<<<H_, 256>>>(Wq, Wk, rff_base, log_bw);
    k_rff<<<dim3(SQ_/16,  BH_), 256>>>(q_atoms, q_weights, 1);
    k_rff<<<dim3(SKV_/16, BH_), 256>>>(k_atoms, k_weights, 0);
    k_va<<<dim3(4, 256), 256>>>(v_atoms, Wv);
    k_mma<true><<<dim3(8, 8, BH_), 256, MMA_SMEM>>>(log_temp);   // scores
    k_softmax<<<BH_*SQ_, 256>>>();
    k_mma<false><<<dim3(4, 8, BH_), 256, MMA_SMEM>>>(log_temp);  // attn @ va
    k_oproj<<<512, 256>>>(Wo, out_atoms);
    k_lw<<<B_*SQ_, 64>>>(Ww, q_logw, out_atoms, out_lw);
}

// round 7
// speedup vs baseline: 2.5145x; 1.0128x over previous
#include <cuda_runtime.h>
#include <cuda_fp16.h>
#include <cstdint>
#include <math.h>

#define B_   4
#define SQ_  1024
#define SKV_ 1024
#define M_   8
#define D_   64
#define H_   8
#define F_   64
#define BH_  (B_*H_)

// ---------------- scratch (device globals; no allocation) ----------------
__device__ float  g_Wqf[H_*D_*F_];
__device__ float  g_Wkf[H_*D_*F_];
__device__ __half g_qrff[(size_t)BH_*SQ_*2*F_];      // [bh][q][128]
__device__ __half g_krff[(size_t)BH_*SKV_*2*F_];     // [bh][k][128]
__device__ __half g_va  [(size_t)BH_*SKV_*512];      // [bh][s][m*64+e]
__device__ float  g_out [(size_t)BH_*SQ_*M_*D_];     // [(b,q,m)][(h,e)]  (oproj layout!)

__device__ __forceinline__ uint32_t s2u(const void* p) {
    uint32_t a;
    asm("{ .reg .u64 t; cvta.to.shared.u64 t, %1; cvt.u32.u64 %0, t; }" : "=r"(a) : "l"(p));
    return a;
}

// ---------------- K1: combined projection-RFF matrices ----------------
__global__ __launch_bounds__(256) void k_combine(const float* __restrict__ Wq,
                                                 const float* __restrict__ Wk,
                                                 const float* __restrict__ base,
                                                 const float* __restrict__ log_bw) {
    __shared__ float sWq[64*64], sWk[64*64], sB[64*64];
    int h = blockIdx.x;
    float inv = expf(-log_bw[h]);
    for (int i = threadIdx.x; i < 4096; i += 256) {
        sWq[i] = Wq[h*4096 + i];
        sWk[i] = Wk[h*4096 + i];
        sB[i]  = base[h*4096 + i] * inv;
    }
    __syncthreads();
    for (int idx = threadIdx.x; idx < 4096; idx += 256) {
        int d = idx >> 6, f = idx & 63;
        float aq = 0.f, ak = 0.f;
        #pragma unroll
        for (int e = 0; e < 64; e++) {
            float bf = sB[e*64 + f];
            aq = fmaf(sWq[e*64 + d], bf, aq);
            ak = fmaf(sWk[e*64 + d], bf, ak);
        }
        g_Wqf[h*4096 + d*64 + f] = aq;
        g_Wkf[h*4096 + d*64 + f] = ak;
    }
}

// ---------------- K2: fused projection + RFF encode (half out) ----------------
__global__ __launch_bounds__(256) void k_rff(const float* __restrict__ atoms,
                                             const float* __restrict__ weights,
                                             int is_q) {
    __shared__ float sWT[64*68];            // [f][d], pad 68
    __shared__ __align__(16) float sAt[4][8][64];
    __shared__ float sw[4][8];
    int bh = blockIdx.y;
    int b = bh >> 3, h = bh & 7;
    const float* Wf = is_q ? g_Wqf : g_Wkf;
    __half* dstbase = (is_q ? g_qrff : g_krff);
    for (int i = threadIdx.x; i < 4096; i += 256) {
        int d = i >> 6, f = i & 63;
        sWT[f*68 + d] = Wf[h*4096 + i];
    }
    int s0 = blockIdx.x * 16;
    int f  = threadIdx.x & 63;
    int sl = threadIdx.x >> 6;
    for (int ss = 0; ss < 16; ss += 4) {
        __syncthreads();
        for (int i = threadIdx.x; i < 2048; i += 256) {
            int si = i >> 9;
            int md = i & 511;
            sAt[si][md >> 6][md & 63] =
                atoms[(size_t)(b*1024 + s0 + ss + si)*512 + md];
        }
        if (threadIdx.x < 32) {
            int si = threadIdx.x >> 3, m = threadIdx.x & 7;
            sw[si][m] = weights[(b*1024 + s0 + ss + si)*8 + m];
        }
        __syncthreads();
        float p[8];
        #pragma unroll
        for (int m = 0; m < 8; m++) p[m] = 0.f;
        #pragma unroll
        for (int dq = 0; dq < 64; dq += 4) {
            float4 wv = *(const float4*)&sWT[f*68 + dq];
            #pragma unroll
            for (int m = 0; m < 8; m++) {
                float4 av = *(const float4*)&sAt[sl][m][dq];
                p[m] = fmaf(av.x, wv.x, p[m]);
                p[m] = fmaf(av.y, wv.y, p[m]);
                p[m] = fmaf(av.z, wv.z, p[m]);
                p[m] = fmaf(av.w, wv.w, p[m]);
            }
        }
        float ac = 0.f, asn = 0.f;
        #pragma unroll
        for (int m = 0; m < 8; m++) {
            float sv, cv;
            __sincosf(p[m], &sv, &cv);
            float w = sw[sl][m];
            ac  = fmaf(w, cv, ac);
            asn = fmaf(w, sv, asn);
        }
        int s = s0 + ss + sl;
        __half* dst = dstbase + ((size_t)bh*1024 + s)*128;
        dst[f]      = __float2half(ac  * 0.125f);
        dst[64 + f] = __float2half(asn * 0.125f);
    }
}

// ---------------- K3: va projection, 128x128 tile, 8x8 microtile ----------------
__global__ __launch_bounds__(256) void k_va(const float* __restrict__ v_atoms,
                                            const float* __restrict__ Wv) {
    __shared__ __align__(16) char sraw[32768];
    float (*sa)[16][128] = (float (*)[16][128])sraw;            // [st][k][row]
    float (*sb)[16][128] = (float (*)[16][128])(sraw + 16384);  // [st][k][col]
    __half (*so)[2][512] = (__half (*)[2][512])sraw;            // [s16][h2][512]

    int rb = blockIdx.y * 128, cb = blockIdx.x * 128;
    int tid = threadIdx.x;
    int tx = tid & 15, ty = tid >> 4;
    float acc[8][8] = {};

    auto load = [&](int st, int kc) {
        #pragma unroll
        for (int i = 0; i < 2; i++) {
            int id = tid + i*256;
            int r = id >> 2, c = (id & 3)*4;
            float4 av = *(const float4*)&v_atoms[(size_t)(rb + r)*64 + kc + c];
            sa[st][c+0][r] = av.x; sa[st][c+1][r] = av.y;
            sa[st][c+2][r] = av.z; sa[st][c+3][r] = av.w;
            float4 bv = *(const float4*)&Wv[(size_t)(cb + r)*64 + kc + c];
            sb[st][c+0][r] = bv.x; sb[st][c+1][r] = bv.y;
            sb[st][c+2][r] = bv.z; sb[st][c+3][r] = bv.w;
        }
    };

    load(0, 0);
    #pragma unroll
    for (int ch = 0; ch < 4; ch++) {
        __syncthreads();
        if (ch < 3) load((ch + 1) & 1, (ch + 1)*16);
        int st = ch & 1;
        #pragma unroll
        for (int k = 0; k < 16; k++) {
            float a[8], bv[8];
            *(float4*)&a[0]  = *(const float4*)&sa[st][k][ty*8];
            *(float4*)&a[4]  = *(const float4*)&sa[st][k][ty*8 + 4];
            *(float4*)&bv[0] = *(const float4*)&sb[st][k][tx*8];
            *(float4*)&bv[4] = *(const float4*)&sb[st][k][tx*8 + 4];
            #pragma unroll
            for (int i = 0; i < 8; i++)
                #pragma unroll
                for (int j = 0; j < 8; j++)
                    acc[i][j] = fmaf(a[i], bv[j], acc[i][j]);
        }
    }
    __syncthreads();
    #pragma unroll
    for (int i = 0; i < 8; i++) {
        int rl = ty*8 + i;
        int s_l = rl >> 3, m = rl & 7;
        __half hv[8];
        #pragma unroll
        for (int j = 0; j < 8; j++) hv[j] = __float2half(acc[i][j]);
        int h_l = (tx*8) >> 6, e0 = (tx*8) & 63;
        *(uint4*)&so[s_l][h_l][m*64 + e0] = *(const uint4*)hv;
    }
    __syncthreads();
    int b = rb >> 13, s0 = (rb >> 3) & 1023;
    int h0 = cb >> 6;
    #pragma unroll
    for (int i = 0; i < 8; i++) {
        int idx = tid + i*256;
        int row = idx >> 6, c = idx & 63;
        int s_l = row >> 1, h_l = row & 1;
        *(uint4*)&g_va[((size_t)((b*8 + h0 + h_l)*1024) + s0 + s_l)*512 + c*8] =
            *(const uint4*)&so[s_l][h_l][c*8];
    }
}

// ---------------- K4: fused flash attention (scores + softmax + attn@va) ----------
// Block: (n-chunk 128, q-tile 128, bh). 8 warps x 16 q-rows each.
// smem: q [128][136], k [2][128][136], v [2][128][136]  = 170KB dynamic
#define FLASH_SMEM 174080
#define TSTR 136
__global__ __launch_bounds__(256) void k_flash(const float* __restrict__ log_temp) {
    extern __shared__ __align__(16) __half fsm[];
    __half* qs = fsm;                     // [128][136]
    __half* ks = fsm + 17408;             // [2][128][136]
    __half* vs = fsm + 17408*3;           // [2][128][136]

    int tid = threadIdx.x, wid = tid >> 5, lid = tid & 31;
    int bh = blockIdx.z, b = bh >> 3, h = bh & 7;
    int qb = blockIdx.y * 128, nb = blockIdx.x * 128;
    const __half* Qg = g_qrff + ((size_t)bh*1024 + qb)*128;
    const __half* Kg = g_krff + (size_t)bh*1024*128;
    const __half* Vg = g_va   + (size_t)bh*1024*512 + nb;
    float temp = __expf(log_temp[h]);

    // ---- loads ----
    auto loadQ = [&]() {
        #pragma unroll
        for (int i = 0; i < 8; i++) {
            int id = tid + i*256;
            int r = id >> 4, c = id & 15;
            uint32_t d = s2u(qs + r*TSTR + c*8);
            asm volatile("cp.async.cg.shared.global [%0], [%1], 16;"
                         :: "r"(d), "l"(Qg + (size_t)r*128 + c*8));
        }
    };
    auto loadKV = [&](int st, int kt) {
        __half* kp = ks + st*17408;
        __half* vp = vs + st*17408;
        #pragma unroll
        for (int i = 0; i < 8; i++) {
            int id = tid + i*256;
            int r = id >> 4, c = id & 15;
            uint32_t d = s2u(kp + r*TSTR + c*8);
            asm volatile("cp.async.cg.shared.global [%0], [%1], 16;"
                         :: "r"(d), "l"(Kg + (size_t)(kt*128 + r)*128 + c*8));
        }
        #pragma unroll
        for (int i = 0; i < 8; i++) {
            int id = tid + i*256;
            int r = id >> 4, c = id & 15;
            uint32_t d = s2u(vp + r*TSTR + c*8);
            asm volatile("cp.async.cg.shared.global [%0], [%1], 16;"
                         :: "r"(d), "l"(Vg + (size_t)(kt*128 + r)*512 + c*8));
        }
        asm volatile("cp.async.commit_group;" ::: "memory");
    };

    loadQ(); loadKV(0, 0);      // group 0 (q + kv0 committed together)
    loadKV(1, 1);               // group 1

    float accO[16][4] = {};
    float m0 = -1e30f, m1 = -1e30f, l0 = 0.f, l1 = 0.f;

    for (int kt = 0; kt < 8; kt++) {
        int st = kt & 1;
        if (kt < 7) asm volatile("cp.async.wait_group 1;" ::: "memory");
        else        asm volatile("cp.async.wait_group 0;" ::: "memory");
        __syncthreads();

        // ---- S = q @ k^T (16 x 128 per warp) ----
        float accS[16][4] = {};
        const __half* kp = ks + st*17408;
        #pragma unroll
        for (int kk = 0; kk < 8; kk++) {
            uint32_t af[4];
            {
                uint32_t addr = s2u(qs + (wid*16 + (lid & 15))*TSTR + kk*16 + ((lid >> 4) << 3));
                asm volatile("ldmatrix.sync.aligned.m8n8.x4.shared.b16 {%0,%1,%2,%3}, [%4];"
                    : "=r"(af[0]), "=r"(af[1]), "=r"(af[2]), "=r"(af[3]) : "r"(addr));
            }
            #pragma unroll
            for (int nj = 0; nj < 8; nj++) {
                uint32_t r0, r1, r2, r3;
                int n = nj*16 + ((lid >> 4) << 3) + (lid & 7);
                int k = kk*16 + (((lid >> 3) & 1) << 3);
                uint32_t addr = s2u(kp + n*TSTR + k);
                asm volatile("ldmatrix.sync.aligned.m8n8.x4.shared.b16 {%0,%1,%2,%3}, [%4];"
                    : "=r"(r0), "=r"(r1), "=r"(r2), "=r"(r3) : "r"(addr));
                asm volatile("mma.sync.aligned.m16n8k16.row.col.f32.f16.f16.f32 "
                    "{%0,%1,%2,%3}, {%4,%5,%6,%7}, {%8,%9}, {%0,%1,%2,%3};"
                    : "+f"(accS[nj*2][0]), "+f"(accS[nj*2][1]),
                      "+f"(accS[nj*2][2]), "+f"(accS[nj*2][3])
                    : "r"(af[0]), "r"(af[1]), "r"(af[2]), "r"(af[3]), "r"(r0), "r"(r1));
                asm volatile("mma.sync.aligned.m16n8k16.row.col.f32.f16.f16.f32 "
                    "{%0,%1,%2,%3}, {%4,%5,%6,%7}, {%8,%9}, {%0,%1,%2,%3};"
                    : "+f"(accS[nj*2+1][0]), "+f"(accS[nj*2+1][1]),
                      "+f"(accS[nj*2+1][2]), "+f"(accS[nj*2+1][3])
                    : "r"(af[0]), "r"(af[1]), "r"(af[2]), "r"(af[3]), "r"(r2), "r"(r3));
            }
        }

        // ---- online softmax (rows r0 = lid>>2, r1 = r0+8) ----
        float mx0 = -1e30f, mx1 = -1e30f;
        #pragma unroll
        for (int ni = 0; ni < 16; ni++) {
            accS[ni][0] *= temp; accS[ni][1] *= temp;
            accS[ni][2] *= temp; accS[ni][3] *= temp;
            mx0 = fmaxf(mx0, fmaxf(accS[ni][0], accS[ni][1]));
            mx1 = fmaxf(mx1, fmaxf(accS[ni][2], accS[ni][3]));
        }
        mx0 = fmaxf(mx0, __shfl_xor_sync(~0u, mx0, 1));
        mx0 = fmaxf(mx0, __shfl_xor_sync(~0u, mx0, 2));
        mx1 = fmaxf(mx1, __shfl_xor_sync(~0u, mx1, 1));
        mx1 = fmaxf(mx1, __shfl_xor_sync(~0u, mx1, 2));
        float mn0 = fmaxf(m0, mx0), mn1 = fmaxf(m1, mx1);
        float sf0 = __expf(m0 - mn0), sf1 = __expf(m1 - mn1);
        m0 = mn0; m1 = mn1;
        float s0 = 0.f, s1 = 0.f;
        uint32_t pf[16][2];
        #pragma unroll
        for (int ni = 0; ni < 16; ni++) {
            float p0 = __expf(accS[ni][0] - m0);
            float p1 = __expf(accS[ni][1] - m0);
            float p2 = __expf(accS[ni][2] - m1);
            float p3 = __expf(accS[ni][3] - m1);
            s0 += p0 + p1; s1 += p2 + p3;
            __half2 h01 = __floats2half2_rn(p0, p1);
            __half2 h23 = __floats2half2_rn(p2, p3);
            pf[ni][0] = *(uint32_t*)&h01;
            pf[ni][1] = *(uint32_t*)&h23;
        }
        s0 += __shfl_xor_sync(~0u, s0, 1); s0 += __shfl_xor_sync(~0u, s0, 2);
        s1 += __shfl_xor_sync(~0u, s1, 1); s1 += __shfl_xor_sync(~0u, s1, 2);
        l0 = l0*sf0 + s0; l1 = l1*sf1 + s1;
        #pragma unroll
        for (int n2 = 0; n2 < 16; n2++) {
            accO[n2][0] *= sf0; accO[n2][1] *= sf0;
            accO[n2][2] *= sf1; accO[n2][3] *= sf1;
        }

        // ---- O += P @ V (P fragments straight from registers) ----
        const __half* vp = vs + st*17408;
        #pragma unroll
        for (int kk2 = 0; kk2 < 8; kk2++) {
            uint32_t a0 = pf[kk2*2][0],   a1 = pf[kk2*2][1];
            uint32_t a2 = pf[kk2*2+1][0], a3 = pf[kk2*2+1][1];
            #pragma unroll
            for (int n2p = 0; n2p < 8; n2p++) {
                uint32_t r0, r1, r2, r3;
                int krow = kk2*16 + (lid & 7) + (((lid >> 3) & 1) << 3);
                int ncol = n2p*16 + ((lid >> 4) << 3);
                uint32_t addr = s2u(vp + krow*TSTR + ncol);
                asm volatile("ldmatrix.sync.aligned.m8n8.x4.trans.shared.b16 {%0,%1,%2,%3}, [%4];"
                    : "=r"(r0), "=r"(r1), "=r"(r2), "=r"(r3) : "r"(addr));
                asm volatile("mma.sync.aligned.m16n8k16.row.col.f32.f16.f16.f32 "
                    "{%0,%1,%2,%3}, {%4,%5,%6,%7}, {%8,%9}, {%0,%1,%2,%3};"
                    : "+f"(accO[n2p*2][0]), "+f"(accO[n2p*2][1]),
                      "+f"(accO[n2p*2][2]), "+f"(accO[n2p*2][3])
                    : "r"(a0), "r"(a1), "r"(a2), "r"(a3), "r"(r0), "r"(r1));
                asm volatile("mma.sync.aligned.m16n8k16.row.col.f32.f16.f16.f32 "
                    "{%0,%1,%2,%3}, {%4,%5,%6,%7}, {%8,%9}, {%0,%1,%2,%3};"
                    : "+f"(accO[n2p*2+1][0]), "+f"(accO[n2p*2+1][1]),
                      "+f"(accO[n2p*2+1][2]), "+f"(accO[n2p*2+1][3])
                    : "r"(a0), "r"(a1), "r"(a2), "r"(a3), "r"(r2), "r"(r3));
            }
        }
        __syncthreads();
        if (kt + 2 < 8) loadKV(st, kt + 2);
    }

    // ---- epilogue: normalize + write in oproj layout [(b,q,m)][(h,e)] ----
    float inv0 = 1.0f / l0, inv1 = 1.0f / l1;
    int q0 = qb + wid*16 + (lid >> 2);
    int q1 = q0 + 8;
    #pragma unroll
    for (int n2 = 0; n2 < 16; n2++) {
        int col = nb + n2*8 + (lid & 3)*2;   // 0..511 = m*64+e
        int m = col >> 6, e = col & 63;
        float* p0 = g_out + ((size_t)(b*1024 + q0)*8 + m)*512 + h*64 + e;
        float* p1 = g_out + ((size_t)(b*1024 + q1)*8 + m)*512 + h*64 + e;
        p0[0] = accO[n2][0] * inv0; p0[1] = accO[n2][1] * inv0;
        p1[0] = accO[n2][2] * inv1; p1[1] = accO[n2][3] * inv1;
    }
}

// ---------------- K7: output projection (now coalesced A loads) ----------------
__global__ __launch_bounds__(256) void k_oproj(const float* __restrict__ Wo,
                                               float* __restrict__ out_atoms) {
    __shared__ float sA[64][65];
    __shared__ float sB[64][65];
    int rb = blockIdx.x * 64;
    int tx = threadIdx.x & 15, ty = threadIdx.x >> 4;
    float acc[4][4] = {};
    for (int h = 0; h < 8; h++) {
        __syncthreads();
        for (int i = threadIdx.x; i < 4096; i += 256) {
            int r = i >> 6, e = i & 63;
            sA[r][e] = g_out[(size_t)(rb + r)*512 + h*64 + e];
            sB[r][e] = Wo[r*512 + h*64 + e];
        }
        __syncthreads();
        #pragma unroll
        for (int k = 0; k < 64; k++) {
            float a[4], bb[4];
            #pragma unroll
            for (int i = 0; i < 4; i++) a[i]  = sA[ty*4 + i][k];
            #pragma unroll
            for (int j = 0; j < 4; j++) bb[j] = sB[tx*4 + j][k];
            #pragma unroll
            for (int i = 0; i < 4; i++)
                #pragma unroll
                for (int j = 0; j < 4; j++)
                    acc[i][j] = fmaf(a[i], bb[j], acc[i][j]);
        }
    }
    #pragma unroll
    for (int i = 0; i < 4; i++)
        #pragma unroll
        for (int j = 0; j < 4; j++)
            out_atoms[(size_t)(rb + ty*4 + i)*64 + tx*4 + j] = acc[i][j];
}

// ---------------- K8: log-weight update ----------------
__global__ __launch_bounds__(64) void k_lw(const float* __restrict__ Ww,
                                           const float* __restrict__ qlw,
                                           const float* __restrict__ out_atoms,
                                           float* __restrict__ out2) {
    __shared__ float mean[64];
    int bq = blockIdx.x;
    int t = threadIdx.x;
    float s = 0.f;
    #pragma unroll
    for (int m = 0; m < 8; m++)
        s += out_atoms[(size_t)(bq*8 + m)*64 + t];
    mean[t] = s * 0.125f;
    __syncthreads();
    if (t < 8) {
        float acc = 0.f;
        #pragma unroll
        for (int d = 0; d < 64; d++)
            acc = fmaf(mean[d], Ww[t*64 + d], acc);
        out2[bq*8 + t] = qlw[bq*8 + t] + acc;
    }
}

// ---------------- launch ----------------
extern "C" void kernel_launch(void* const* d_in, const int* in_sizes, int n_in,
                              void* d_out, int out_size) {
    const float* q_atoms   = (const float*)d_in[0];
    const float* q_weights = (const float*)d_in[1];
    const float* q_logw    = (const float*)d_in[2];
    const float* k_atoms   = (const float*)d_in[3];
    const float* k_weights = (const float*)d_in[4];
    const float* v_atoms   = (const float*)d_in[5];
    const float* Wq        = (const float*)d_in[6];
    const float* Wk        = (const float*)d_in[7];
    const float* Wv        = (const float*)d_in[8];
    const float* Wo        = (const float*)d_in[9];
    const float* Ww        = (const float*)d_in[10];
    const float* log_bw    = (const float*)d_in[11];
    const float* log_temp  = (const float*)d_in[12];
    const float* rff_base  = (const float*)d_in[13];

    float* out_atoms = (float*)d_out;
    float* out_lw    = (float*)d_out + (size_t)B_*SQ_*M_*D_;

    cudaFuncSetAttribute(k_flash, cudaFuncAttributeMaxDynamicSharedMemorySize, FLASH_SMEM);

    k_combine<<<H_, 256>>>(Wq, Wk, rff_base, log_bw);
    k_rff<<<dim3(SQ_/16,  BH_), 256>>>(q_atoms, q_weights, 1);
    k_rff<<<dim3(SKV_/16, BH_), 256>>>(k_atoms, k_weights, 0);
    k_va<<<dim3(4, 256), 256>>>(v_atoms, Wv);
    k_flash<<<dim3(4, 8, BH_), 256, FLASH_SMEM>>>(log_temp);
    k_oproj<<<512, 256>>>(Wo, out_atoms);
    k_lw<<<B_*SQ_, 64>>>(Ww, q_logw, out_atoms, out_lw);
}

// round 8
// speedup vs baseline: 2.5281x; 1.0054x over previous
#include <cuda_runtime.h>
#include <cuda_fp16.h>
#include <cstdint>
#include <math.h>

#define B_   4
#define SQ_  1024
#define SKV_ 1024
#define M_   8
#define D_   64
#define H_   8
#define F_   64
#define BH_  (B_*H_)

// ---------------- scratch (device globals; no allocation) ----------------
__device__ float  g_Wqf[H_*D_*F_];
__device__ float  g_Wkf[H_*D_*F_];
__device__ __half g_qrff[(size_t)BH_*SQ_*2*F_];      // [bh][q][128]
__device__ __half g_krff[(size_t)BH_*SKV_*2*F_];     // [bh][k][128]
__device__ __half g_va  [(size_t)BH_*SKV_*512];      // [bh][s][m*64+e]
__device__ float  g_out [(size_t)BH_*SQ_*M_*D_];     // [(b,q,m)][(h,e)]  (oproj layout!)

__device__ __forceinline__ uint32_t s2u(const void* p) {
    uint32_t a;
    asm("{ .reg .u64 t; cvta.to.shared.u64 t, %1; cvt.u32.u64 %0, t; }" : "=r"(a) : "l"(p));
    return a;
}

// ---------------- K1: combined projection-RFF matrices ----------------
__global__ __launch_bounds__(256) void k_combine(const float* __restrict__ Wq,
                                                 const float* __restrict__ Wk,
                                                 const float* __restrict__ base,
                                                 const float* __restrict__ log_bw) {
    __shared__ float sWq[64*64], sWk[64*64], sB[64*64];
    int h = blockIdx.x;
    float inv = expf(-log_bw[h]);
    for (int i = threadIdx.x; i < 4096; i += 256) {
        sWq[i] = Wq[h*4096 + i];
        sWk[i] = Wk[h*4096 + i];
        sB[i]  = base[h*4096 + i] * inv;
    }
    __syncthreads();
    for (int idx = threadIdx.x; idx < 4096; idx += 256) {
        int d = idx >> 6, f = idx & 63;
        float aq = 0.f, ak = 0.f;
        #pragma unroll
        for (int e = 0; e < 64; e++) {
            float bf = sB[e*64 + f];
            aq = fmaf(sWq[e*64 + d], bf, aq);
            ak = fmaf(sWk[e*64 + d], bf, ak);
        }
        g_Wqf[h*4096 + d*64 + f] = aq;
        g_Wkf[h*4096 + d*64 + f] = ak;
    }
}

// ---------------- K2: fused projection + RFF encode (half out) ----------------
__global__ __launch_bounds__(256) void k_rff(const float* __restrict__ atoms,
                                             const float* __restrict__ weights,
                                             int is_q) {
    __shared__ float sWT[64*68];            // [f][d], pad 68
    __shared__ __align__(16) float sAt[4][8][64];
    __shared__ float sw[4][8];
    int bh = blockIdx.y;
    int b = bh >> 3, h = bh & 7;
    const float* Wf = is_q ? g_Wqf : g_Wkf;
    __half* dstbase = (is_q ? g_qrff : g_krff);
    for (int i = threadIdx.x; i < 4096; i += 256) {
        int d = i >> 6, f = i & 63;
        sWT[f*68 + d] = Wf[h*4096 + i];
    }
    int s0 = blockIdx.x * 16;
    int f  = threadIdx.x & 63;
    int sl = threadIdx.x >> 6;
    for (int ss = 0; ss < 16; ss += 4) {
        __syncthreads();
        for (int i = threadIdx.x; i < 2048; i += 256) {
            int si = i >> 9;
            int md = i & 511;
            sAt[si][md >> 6][md & 63] =
                atoms[(size_t)(b*1024 + s0 + ss + si)*512 + md];
        }
        if (threadIdx.x < 32) {
            int si = threadIdx.x >> 3, m = threadIdx.x & 7;
            sw[si][m] = weights[(b*1024 + s0 + ss + si)*8 + m];
        }
        __syncthreads();
        float p[8];
        #pragma unroll
        for (int m = 0; m < 8; m++) p[m] = 0.f;
        #pragma unroll
        for (int dq = 0; dq < 64; dq += 4) {
            float4 wv = *(const float4*)&sWT[f*68 + dq];
            #pragma unroll
            for (int m = 0; m < 8; m++) {
                float4 av = *(const float4*)&sAt[sl][m][dq];
                p[m] = fmaf(av.x, wv.x, p[m]);
                p[m] = fmaf(av.y, wv.y, p[m]);
                p[m] = fmaf(av.z, wv.z, p[m]);
                p[m] = fmaf(av.w, wv.w, p[m]);
            }
        }
        float ac = 0.f, asn = 0.f;
        #pragma unroll
        for (int m = 0; m < 8; m++) {
            float sv, cv;
            __sincosf(p[m], &sv, &cv);
            float w = sw[sl][m];
            ac  = fmaf(w, cv, ac);
            asn = fmaf(w, sv, asn);
        }
        int s = s0 + ss + sl;
        __half* dst = dstbase + ((size_t)bh*1024 + s)*128;
        dst[f]      = __float2half(ac  * 0.125f);
        dst[64 + f] = __float2half(asn * 0.125f);
    }
}

// ---------------- K3: va projection, 128x128 tile, 8x8 microtile ----------------
__global__ __launch_bounds__(256) void k_va(const float* __restrict__ v_atoms,
                                            const float* __restrict__ Wv) {
    __shared__ __align__(16) char sraw[32768];
    float (*sa)[16][128] = (float (*)[16][128])sraw;            // [st][k][row]
    float (*sb)[16][128] = (float (*)[16][128])(sraw + 16384);  // [st][k][col]
    __half (*so)[2][512] = (__half (*)[2][512])sraw;            // [s16][h2][512]

    int rb = blockIdx.y * 128, cb = blockIdx.x * 128;
    int tid = threadIdx.x;
    int tx = tid & 15, ty = tid >> 4;
    float acc[8][8] = {};

    auto load = [&](int st, int kc) {
        #pragma unroll
        for (int i = 0; i < 2; i++) {
            int id = tid + i*256;
            int r = id >> 2, c = (id & 3)*4;
            float4 av = *(const float4*)&v_atoms[(size_t)(rb + r)*64 + kc + c];
            sa[st][c+0][r] = av.x; sa[st][c+1][r] = av.y;
            sa[st][c+2][r] = av.z; sa[st][c+3][r] = av.w;
            float4 bv = *(const float4*)&Wv[(size_t)(cb + r)*64 + kc + c];
            sb[st][c+0][r] = bv.x; sb[st][c+1][r] = bv.y;
            sb[st][c+2][r] = bv.z; sb[st][c+3][r] = bv.w;
        }
    };

    load(0, 0);
    #pragma unroll
    for (int ch = 0; ch < 4; ch++) {
        __syncthreads();
        if (ch < 3) load((ch + 1) & 1, (ch + 1)*16);
        int st = ch & 1;
        #pragma unroll
        for (int k = 0; k < 16; k++) {
            float a[8], bv[8];
            *(float4*)&a[0]  = *(const float4*)&sa[st][k][ty*8];
            *(float4*)&a[4]  = *(const float4*)&sa[st][k][ty*8 + 4];
            *(float4*)&bv[0] = *(const float4*)&sb[st][k][tx*8];
            *(float4*)&bv[4] = *(const float4*)&sb[st][k][tx*8 + 4];
            #pragma unroll
            for (int i = 0; i < 8; i++)
                #pragma unroll
                for (int j = 0; j < 8; j++)
                    acc[i][j] = fmaf(a[i], bv[j], acc[i][j]);
        }
    }
    __syncthreads();
    #pragma unroll
    for (int i = 0; i < 8; i++) {
        int rl = ty*8 + i;
        int s_l = rl >> 3, m = rl & 7;
        __half hv[8];
        #pragma unroll
        for (int j = 0; j < 8; j++) hv[j] = __float2half(acc[i][j]);
        int h_l = (tx*8) >> 6, e0 = (tx*8) & 63;
        *(uint4*)&so[s_l][h_l][m*64 + e0] = *(const uint4*)hv;
    }
    __syncthreads();
    int b = rb >> 13, s0 = (rb >> 3) & 1023;
    int h0 = cb >> 6;
    #pragma unroll
    for (int i = 0; i < 8; i++) {
        int idx = tid + i*256;
        int row = idx >> 6, c = idx & 63;
        int s_l = row >> 1, h_l = row & 1;
        *(uint4*)&g_va[((size_t)((b*8 + h0 + h_l)*1024) + s0 + s_l)*512 + c*8] =
            *(const uint4*)&so[s_l][h_l][c*8];
    }
}

// ---------------- K4: fused flash attention (scores + softmax + attn@va) ----------
// Block: (n-chunk 128, q-tile 128, bh). 8 warps x 16 q-rows each.
// smem: q [128][136], k [2][128][136], v [2][128][136]  = 170KB dynamic
#define FLASH_SMEM 174080
#define TSTR 136
__global__ __launch_bounds__(256) void k_flash(const float* __restrict__ log_temp) {
    extern __shared__ __align__(16) __half fsm[];
    __half* qs = fsm;                     // [128][136]
    __half* ks = fsm + 17408;             // [2][128][136]
    __half* vs = fsm + 17408*3;           // [2][128][136]

    int tid = threadIdx.x, wid = tid >> 5, lid = tid & 31;
    int bh = blockIdx.z, b = bh >> 3, h = bh & 7;
    int qb = blockIdx.y * 128, nb = blockIdx.x * 128;
    const __half* Qg = g_qrff + ((size_t)bh*1024 + qb)*128;
    const __half* Kg = g_krff + (size_t)bh*1024*128;
    const __half* Vg = g_va   + (size_t)bh*1024*512 + nb;
    float temp = __expf(log_temp[h]);

    // ---- loads ----
    auto loadQ = [&]() {
        #pragma unroll
        for (int i = 0; i < 8; i++) {
            int id = tid + i*256;
            int r = id >> 4, c = id & 15;
            uint32_t d = s2u(qs + r*TSTR + c*8);
            asm volatile("cp.async.cg.shared.global [%0], [%1], 16;"
                         :: "r"(d), "l"(Qg + (size_t)r*128 + c*8));
        }
    };
    auto loadKV = [&](int st, int kt) {
        __half* kp = ks + st*17408;
        __half* vp = vs + st*17408;
        #pragma unroll
        for (int i = 0; i < 8; i++) {
            int id = tid + i*256;
            int r = id >> 4, c = id & 15;
            uint32_t d = s2u(kp + r*TSTR + c*8);
            asm volatile("cp.async.cg.shared.global [%0], [%1], 16;"
                         :: "r"(d), "l"(Kg + (size_t)(kt*128 + r)*128 + c*8));
        }
        #pragma unroll
        for (int i = 0; i < 8; i++) {
            int id = tid + i*256;
            int r = id >> 4, c = id & 15;
            uint32_t d = s2u(vp + r*TSTR + c*8);
            asm volatile("cp.async.cg.shared.global [%0], [%1], 16;"
                         :: "r"(d), "l"(Vg + (size_t)(kt*128 + r)*512 + c*8));
        }
        asm volatile("cp.async.commit_group;" ::: "memory");
    };

    loadQ(); loadKV(0, 0);      // group 0 (q + kv0 committed together)
    loadKV(1, 1);               // group 1

    float accO[16][4] = {};
    float m0 = -1e30f, m1 = -1e30f, l0 = 0.f, l1 = 0.f;

    for (int kt = 0; kt < 8; kt++) {
        int st = kt & 1;
        if (kt < 7) asm volatile("cp.async.wait_group 1;" ::: "memory");
        else        asm volatile("cp.async.wait_group 0;" ::: "memory");
        __syncthreads();

        // ---- S = q @ k^T (16 x 128 per warp) ----
        float accS[16][4] = {};
        const __half* kp = ks + st*17408;
        #pragma unroll
        for (int kk = 0; kk < 8; kk++) {
            uint32_t af[4];
            {
                uint32_t addr = s2u(qs + (wid*16 + (lid & 15))*TSTR + kk*16 + ((lid >> 4) << 3));
                asm volatile("ldmatrix.sync.aligned.m8n8.x4.shared.b16 {%0,%1,%2,%3}, [%4];"
                    : "=r"(af[0]), "=r"(af[1]), "=r"(af[2]), "=r"(af[3]) : "r"(addr));
            }
            #pragma unroll
            for (int nj = 0; nj < 8; nj++) {
                uint32_t r0, r1, r2, r3;
                int n = nj*16 + ((lid >> 4) << 3) + (lid & 7);
                int k = kk*16 + (((lid >> 3) & 1) << 3);
                uint32_t addr = s2u(kp + n*TSTR + k);
                asm volatile("ldmatrix.sync.aligned.m8n8.x4.shared.b16 {%0,%1,%2,%3}, [%4];"
                    : "=r"(r0), "=r"(r1), "=r"(r2), "=r"(r3) : "r"(addr));
                asm volatile("mma.sync.aligned.m16n8k16.row.col.f32.f16.f16.f32 "
                    "{%0,%1,%2,%3}, {%4,%5,%6,%7}, {%8,%9}, {%0,%1,%2,%3};"
                    : "+f"(accS[nj*2][0]), "+f"(accS[nj*2][1]),
                      "+f"(accS[nj*2][2]), "+f"(accS[nj*2][3])
                    : "r"(af[0]), "r"(af[1]), "r"(af[2]), "r"(af[3]), "r"(r0), "r"(r1));
                asm volatile("mma.sync.aligned.m16n8k16.row.col.f32.f16.f16.f32 "
                    "{%0,%1,%2,%3}, {%4,%5,%6,%7}, {%8,%9}, {%0,%1,%2,%3};"
                    : "+f"(accS[nj*2+1][0]), "+f"(accS[nj*2+1][1]),
                      "+f"(accS[nj*2+1][2]), "+f"(accS[nj*2+1][3])
                    : "r"(af[0]), "r"(af[1]), "r"(af[2]), "r"(af[3]), "r"(r2), "r"(r3));
            }
        }

        // ---- online softmax (rows r0 = lid>>2, r1 = r0+8) ----
        float mx0 = -1e30f, mx1 = -1e30f;
        #pragma unroll
        for (int ni = 0; ni < 16; ni++) {
            accS[ni][0] *= temp; accS[ni][1] *= temp;
            accS[ni][2] *= temp; accS[ni][3] *= temp;
            mx0 = fmaxf(mx0, fmaxf(accS[ni][0], accS[ni][1]));
            mx1 = fmaxf(mx1, fmaxf(accS[ni][2], accS[ni][3]));
        }
        mx0 = fmaxf(mx0, __shfl_xor_sync(~0u, mx0, 1));
        mx0 = fmaxf(mx0, __shfl_xor_sync(~0u, mx0, 2));
        mx1 = fmaxf(mx1, __shfl_xor_sync(~0u, mx1, 1));
        mx1 = fmaxf(mx1, __shfl_xor_sync(~0u, mx1, 2));
        float mn0 = fmaxf(m0, mx0), mn1 = fmaxf(m1, mx1);
        float sf0 = __expf(m0 - mn0), sf1 = __expf(m1 - mn1);
        m0 = mn0; m1 = mn1;
        float s0 = 0.f, s1 = 0.f;
        uint32_t pf[16][2];
        #pragma unroll
        for (int ni = 0; ni < 16; ni++) {
            float p0 = __expf(accS[ni][0] - m0);
            float p1 = __expf(accS[ni][1] - m0);
            float p2 = __expf(accS[ni][2] - m1);
            float p3 = __expf(accS[ni][3] - m1);
            s0 += p0 + p1; s1 += p2 + p3;
            __half2 h01 = __floats2half2_rn(p0, p1);
            __half2 h23 = __floats2half2_rn(p2, p3);
            pf[ni][0] = *(uint32_t*)&h01;
            pf[ni][1] = *(uint32_t*)&h23;
        }
        s0 += __shfl_xor_sync(~0u, s0, 1); s0 += __shfl_xor_sync(~0u, s0, 2);
        s1 += __shfl_xor_sync(~0u, s1, 1); s1 += __shfl_xor_sync(~0u, s1, 2);
        l0 = l0*sf0 + s0; l1 = l1*sf1 + s1;
        #pragma unroll
        for (int n2 = 0; n2 < 16; n2++) {
            accO[n2][0] *= sf0; accO[n2][1] *= sf0;
            accO[n2][2] *= sf1; accO[n2][3] *= sf1;
        }

        // ---- O += P @ V (P fragments straight from registers) ----
        const __half* vp = vs + st*17408;
        #pragma unroll
        for (int kk2 = 0; kk2 < 8; kk2++) {
            uint32_t a0 = pf[kk2*2][0],   a1 = pf[kk2*2][1];
            uint32_t a2 = pf[kk2*2+1][0], a3 = pf[kk2*2+1][1];
            #pragma unroll
            for (int n2p = 0; n2p < 8; n2p++) {
                uint32_t r0, r1, r2, r3;
                int krow = kk2*16 + (lid & 7) + (((lid >> 3) & 1) << 3);
                int ncol = n2p*16 + ((lid >> 4) << 3);
                uint32_t addr = s2u(vp + krow*TSTR + ncol);
                asm volatile("ldmatrix.sync.aligned.m8n8.x4.trans.shared.b16 {%0,%1,%2,%3}, [%4];"
                    : "=r"(r0), "=r"(r1), "=r"(r2), "=r"(r3) : "r"(addr));
                asm volatile("mma.sync.aligned.m16n8k16.row.col.f32.f16.f16.f32 "
                    "{%0,%1,%2,%3}, {%4,%5,%6,%7}, {%8,%9}, {%0,%1,%2,%3};"
                    : "+f"(accO[n2p*2][0]), "+f"(accO[n2p*2][1]),
                      "+f"(accO[n2p*2][2]), "+f"(accO[n2p*2][3])
                    : "r"(a0), "r"(a1), "r"(a2), "r"(a3), "r"(r0), "r"(r1));
                asm volatile("mma.sync.aligned.m16n8k16.row.col.f32.f16.f16.f32 "
                    "{%0,%1,%2,%3}, {%4,%5,%6,%7}, {%8,%9}, {%0,%1,%2,%3};"
                    : "+f"(accO[n2p*2+1][0]), "+f"(accO[n2p*2+1][1]),
                      "+f"(accO[n2p*2+1][2]), "+f"(accO[n2p*2+1][3])
                    : "r"(a0), "r"(a1), "r"(a2), "r"(a3), "r"(r2), "r"(r3));
            }
        }
        __syncthreads();
        if (kt + 2 < 8) loadKV(st, kt + 2);
    }

    // ---- epilogue: normalize + write in oproj layout [(b,q,m)][(h,e)] ----
    float inv0 = 1.0f / l0, inv1 = 1.0f / l1;
    int q0 = qb + wid*16 + (lid >> 2);
    int q1 = q0 + 8;
    #pragma unroll
    for (int n2 = 0; n2 < 16; n2++) {
        int col = nb + n2*8 + (lid & 3)*2;   // 0..511 = m*64+e
        int m = col >> 6, e = col & 63;
        float* p0 = g_out + ((size_t)(b*1024 + q0)*8 + m)*512 + h*64 + e;
        float* p1 = g_out + ((size_t)(b*1024 + q1)*8 + m)*512 + h*64 + e;
        p0[0] = accO[n2][0] * inv0; p0[1] = accO[n2][1] * inv0;
        p1[0] = accO[n2][2] * inv1; p1[1] = accO[n2][3] * inv1;
    }
}

// ---------------- K7: output projection (now coalesced A loads) ----------------
__global__ __launch_bounds__(256) void k_oproj(const float* __restrict__ Wo,
                                               float* __restrict__ out_atoms) {
    __shared__ float sA[64][65];
    __shared__ float sB[64][65];
    int rb = blockIdx.x * 64;
    int tx = threadIdx.x & 15, ty = threadIdx.x >> 4;
    float acc[4][4] = {};
    for (int h = 0; h < 8; h++) {
        __syncthreads();
        for (int i = threadIdx.x; i < 4096; i += 256) {
            int r = i >> 6, e = i & 63;
            sA[r][e] = g_out[(size_t)(rb + r)*512 + h*64 + e];
            sB[r][e] = Wo[r*512 + h*64 + e];
        }
        __syncthreads();
        #pragma unroll
        for (int k = 0; k < 64; k++) {
            float a[4], bb[4];
            #pragma unroll
            for (int i = 0; i < 4; i++) a[i]  = sA[ty*4 + i][k];
            #pragma unroll
            for (int j = 0; j < 4; j++) bb[j] = sB[tx*4 + j][k];
            #pragma unroll
            for (int i = 0; i < 4; i++)
                #pragma unroll
                for (int j = 0; j < 4; j++)
                    acc[i][j] = fmaf(a[i], bb[j], acc[i][j]);
        }
    }
    #pragma unroll
    for (int i = 0; i < 4; i++)
        #pragma unroll
        for (int j = 0; j < 4; j++)
            out_atoms[(size_t)(rb + ty*4 + i)*64 + tx*4 + j] = acc[i][j];
}

// ---------------- K8: log-weight update ----------------
__global__ __launch_bounds__(64) void k_lw(const float* __restrict__ Ww,
                                           const float* __restrict__ qlw,
                                           const float* __restrict__ out_atoms,
                                           float* __restrict__ out2) {
    __shared__ float mean[64];
    int bq = blockIdx.x;
    int t = threadIdx.x;
    float s = 0.f;
    #pragma unroll
    for (int m = 0; m < 8; m++)
        s += out_atoms[(size_t)(bq*8 + m)*64 + t];
    mean[t] = s * 0.125f;
    __syncthreads();
    if (t < 8) {
        float acc = 0.f;
        #pragma unroll
        for (int d = 0; d < 64; d++)
            acc = fmaf(mean[d], Ww[t*64 + d], acc);
        out2[bq*8 + t] = qlw[bq*8 + t] + acc;
    }
}

// ---------------- launch ----------------
extern "C" void kernel_launch(void* const* d_in, const int* in_sizes, int n_in,
                              void* d_out, int out_size) {
    const float* q_atoms   = (const float*)d_in[0];
    const float* q_weights = (const float*)d_in[1];
    const float* q_logw    = (const float*)d_in[2];
    const float* k_atoms   = (const float*)d_in[3];
    const float* k_weights = (const float*)d_in[4];
    const float* v_atoms   = (const float*)d_in[5];
    const float* Wq        = (const float*)d_in[6];
    const float* Wk        = (const float*)d_in[7];
    const float* Wv        = (const float*)d_in[8];
    const float* Wo        = (const float*)d_in[9];
    const float* Ww        = (const float*)d_in[10];
    const float* log_bw    = (const float*)d_in[11];
    const float* log_temp  = (const float*)d_in[12];
    const float* rff_base  = (const float*)d_in[13];

    float* out_atoms = (float*)d_out;
    float* out_lw    = (float*)d_out + (size_t)B_*SQ_*M_*D_;

    cudaFuncSetAttribute(k_flash, cudaFuncAttributeMaxDynamicSharedMemorySize, FLASH_SMEM);

    k_combine<<<H_, 256>>>(Wq, Wk, rff_base, log_bw);
    k_rff<<<dim3(SQ_/16,  BH_), 256>>>(q_atoms, q_weights, 1);
    k_rff<<<dim3(SKV_/16, BH_), 256>>>(k_atoms, k_weights, 0);
    k_va<<<dim3(4, 256), 256>>>(v_atoms, Wv);
    k_flash<<<dim3(4, 8, BH_), 256, FLASH_SMEM>>>(log_temp);
    k_oproj<<<512, 256>>>(Wo, out_atoms);
    k_lw<<<B_*SQ_, 64>>>(Ww, q_logw, out_atoms, out_lw);
}

// round 10
// speedup vs baseline: 3.1409x; 1.2424x over previous
#include <cuda_runtime.h>
#include <cuda_fp16.h>
#include <cstdint>
#include <math.h>

#define B_   4
#define SQ_  1024
#define SKV_ 1024
#define M_   8
#define D_   64
#define H_   8
#define F_   64
#define BH_  (B_*H_)

// ---------------- scratch (device globals; no allocation) ----------------
__device__ float  g_Wqf[H_*D_*F_];
__device__ float  g_Wkf[H_*D_*F_];
__device__ __half g_qrff[(size_t)BH_*SQ_*2*F_];      // [bh][q][128]
__device__ __half g_krff[(size_t)BH_*SKV_*2*F_];     // [bh][k][128]
__device__ __half g_vah [(size_t)B_*SKV_*M_*D_];     // v_atoms in half (row-major)
__device__ __half g_Wvh [512*64];
__device__ __half g_Woh [64*512];
__device__ __half g_va  [(size_t)BH_*SKV_*512];      // [bh][s][m*64+e]
__device__ __half g_outh[(size_t)BH_*SQ_*M_*D_];     // [(b,q,m)][(h,e)] half

__device__ __forceinline__ uint32_t s2u(const void* p) {
    uint32_t a;
    asm("{ .reg .u64 t; cvta.to.shared.u64 t, %1; cvt.u32.u64 %0, t; }" : "=r"(a) : "l"(p));
    return a;
}

// ---------------- K0: convert v_atoms / Wv / Wo to half ----------------
__global__ __launch_bounds__(256) void k_cvt(const float* __restrict__ va,
                                             const float* __restrict__ Wv,
                                             const float* __restrict__ Wo) {
    int i = blockIdx.x*256 + threadIdx.x;          // grid 2048 -> i < 524288
    float4 v = *(const float4*)&va[(size_t)i*4];
    __half2 h0 = __floats2half2_rn(v.x, v.y), h1 = __floats2half2_rn(v.z, v.w);
    uint2 pk; pk.x = *(uint32_t*)&h0; pk.y = *(uint32_t*)&h1;
    *(uint2*)&g_vah[(size_t)i*4] = pk;
    if (i < 8192) {
        float4 a = *(const float4*)&Wv[i*4];
        __half2 a0 = __floats2half2_rn(a.x, a.y), a1 = __floats2half2_rn(a.z, a.w);
        uint2 p2; p2.x = *(uint32_t*)&a0; p2.y = *(uint32_t*)&a1;
        *(uint2*)&g_Wvh[i*4] = p2;
        float4 b = *(const float4*)&Wo[i*4];
        __half2 b0 = __floats2half2_rn(b.x, b.y), b1 = __floats2half2_rn(b.z, b.w);
        uint2 p3; p3.x = *(uint32_t*)&b0; p3.y = *(uint32_t*)&b1;
        *(uint2*)&g_Woh[i*4] = p3;
    }
}

// ---------------- K1: combined projection-RFF matrices ----------------
__global__ __launch_bounds__(256) void k_combine(const float* __restrict__ Wq,
                                                 const float* __restrict__ Wk,
                                                 const float* __restrict__ base,
                                                 const float* __restrict__ log_bw) {
    __shared__ float sWq[64*64], sWk[64*64], sB[64*64];
    int h = blockIdx.x;
    float inv = expf(-log_bw[h]);
    for (int i = threadIdx.x; i < 4096; i += 256) {
        sWq[i] = Wq[h*4096 + i];
        sWk[i] = Wk[h*4096 + i];
        sB[i]  = base[h*4096 + i] * inv;
    }
    __syncthreads();
    for (int idx = threadIdx.x; idx < 4096; idx += 256) {
        int d = idx >> 6, f = idx & 63;
        float aq = 0.f, ak = 0.f;
        #pragma unroll
        for (int e = 0; e < 64; e++) {
            float bf = sB[e*64 + f];
            aq = fmaf(sWq[e*64 + d], bf, aq);
            ak = fmaf(sWk[e*64 + d], bf, ak);
        }
        g_Wqf[h*4096 + d*64 + f] = aq;
        g_Wkf[h*4096 + d*64 + f] = ak;
    }
}

// ---------------- K2: fused projection + RFF encode (half out) ----------------
__global__ __launch_bounds__(256) void k_rff(const float* __restrict__ atoms,
                                             const float* __restrict__ weights,
                                             int is_q) {
    __shared__ float sWT[64*68];
    __shared__ __align__(16) float sAt[4][8][64];
    __shared__ float sw[4][8];
    int bh = blockIdx.y;
    int b = bh >> 3, h = bh & 7;
    const float* Wf = is_q ? g_Wqf : g_Wkf;
    __half* dstbase = (is_q ? g_qrff : g_krff);
    for (int i = threadIdx.x; i < 4096; i += 256) {
        int d = i >> 6, f = i & 63;
        sWT[f*68 + d] = Wf[h*4096 + i];
    }
    int s0 = blockIdx.x * 16;
    int f  = threadIdx.x & 63;
    int sl = threadIdx.x >> 6;
    for (int ss = 0; ss < 16; ss += 4) {
        __syncthreads();
        for (int i = threadIdx.x; i < 2048; i += 256) {
            int si = i >> 9;
            int md = i & 511;
            sAt[si][md >> 6][md & 63] =
                atoms[(size_t)(b*1024 + s0 + ss + si)*512 + md];
        }
        if (threadIdx.x < 32) {
            int si = threadIdx.x >> 3, m = threadIdx.x & 7;
            sw[si][m] = weights[(b*1024 + s0 + ss + si)*8 + m];
        }
        __syncthreads();
        float p[8];
        #pragma unroll
        for (int m = 0; m < 8; m++) p[m] = 0.f;
        #pragma unroll
        for (int dq = 0; dq < 64; dq += 4) {
            float4 wv = *(const float4*)&sWT[f*68 + dq];
            #pragma unroll
            for (int m = 0; m < 8; m++) {
                float4 av = *(const float4*)&sAt[sl][m][dq];
                p[m] = fmaf(av.x, wv.x, p[m]);
                p[m] = fmaf(av.y, wv.y, p[m]);
                p[m] = fmaf(av.z, wv.z, p[m]);
                p[m] = fmaf(av.w, wv.w, p[m]);
            }
        }
        float ac = 0.f, asn = 0.f;
        #pragma unroll
        for (int m = 0; m < 8; m++) {
            float sv, cv;
            __sincosf(p[m], &sv, &cv);
            float w = sw[sl][m];
            ac  = fmaf(w, cv, ac);
            asn = fmaf(w, sv, asn);
        }
        int s = s0 + ss + sl;
        __half* dst = dstbase + ((size_t)bh*1024 + s)*128;
        dst[f]      = __float2half(ac  * 0.125f);
        dst[64 + f] = __float2half(asn * 0.125f);
    }
}

// ---------------- K3: va projection via HMMA (M=32768, N=512, K=64) ----------
// smem arena 36864 B: inputs sA/sB, then ALIASED output staging (inputs dead).
__global__ __launch_bounds__(256) void k_va2() {
    __shared__ __align__(16) char sraw[36864];
    __half (*sA)[72] = (__half (*)[72])sraw;                 // [128][72]  (18432 B)
    __half (*sB)[72] = (__half (*)[72])(sraw + 18432);       // [128][72]  (18432 B)
    __half (*so)[2][512] = (__half (*)[2][512])sraw;         // [16][2][512] (32768 B, aliased)

    int tid = threadIdx.x, wid = tid >> 5, lid = tid & 31;
    int cb = blockIdx.x * 128, rb = blockIdx.y * 128;
    int warp_m = (wid & 3) * 32, warp_n = (wid >> 2) * 64;

    #pragma unroll
    for (int i = 0; i < 4; i++) {
        int id = tid + i*256;          // 0..1023
        int r = id >> 3, c = id & 7;
        uint32_t d = s2u(&sA[r][c*8]);
        asm volatile("cp.async.cg.shared.global [%0], [%1], 16;"
                     :: "r"(d), "l"(g_vah + (size_t)(rb + r)*64 + c*8));
    }
    #pragma unroll
    for (int i = 0; i < 4; i++) {
        int id = tid + i*256;
        int r = id >> 3, c = id & 7;
        uint32_t d = s2u(&sB[r][c*8]);
        asm volatile("cp.async.cg.shared.global [%0], [%1], 16;"
                     :: "r"(d), "l"(g_Wvh + (size_t)(cb + r)*64 + c*8));
    }
    asm volatile("cp.async.commit_group;" ::: "memory");
    asm volatile("cp.async.wait_group 0;" ::: "memory");
    __syncthreads();

    float acc[2][8][4] = {};
    #pragma unroll
    for (int kk = 0; kk < 4; kk++) {
        uint32_t af[2][4];
        #pragma unroll
        for (int mi = 0; mi < 2; mi++) {
            uint32_t addr = s2u(&sA[warp_m + mi*16 + (lid & 15)][kk*16 + ((lid >> 4) << 3)]);
            asm volatile("ldmatrix.sync.aligned.m8n8.x4.shared.b16 {%0,%1,%2,%3}, [%4];"
                : "=r"(af[mi][0]), "=r"(af[mi][1]), "=r"(af[mi][2]), "=r"(af[mi][3])
                : "r"(addr));
        }
        #pragma unroll
        for (int nj = 0; nj < 4; nj++) {
            uint32_t r0, r1, r2, r3;
            int n = warp_n + nj*16 + ((lid >> 4) << 3) + (lid & 7);
            int k = kk*16 + (((lid >> 3) & 1) << 3);
            uint32_t addr = s2u(&sB[n][k]);
            asm volatile("ldmatrix.sync.aligned.m8n8.x4.shared.b16 {%0,%1,%2,%3}, [%4];"
                : "=r"(r0), "=r"(r1), "=r"(r2), "=r"(r3) : "r"(addr));
            #pragma unroll
            for (int mi = 0; mi < 2; mi++) {
                asm volatile("mma.sync.aligned.m16n8k16.row.col.f32.f16.f16.f32 "
                    "{%0,%1,%2,%3}, {%4,%5,%6,%7}, {%8,%9}, {%0,%1,%2,%3};"
                    : "+f"(acc[mi][nj*2][0]), "+f"(acc[mi][nj*2][1]),
                      "+f"(acc[mi][nj*2][2]), "+f"(acc[mi][nj*2][3])
                    : "r"(af[mi][0]), "r"(af[mi][1]), "r"(af[mi][2]), "r"(af[mi][3]),
                      "r"(r0), "r"(r1));
                asm volatile("mma.sync.aligned.m16n8k16.row.col.f32.f16.f16.f32 "
                    "{%0,%1,%2,%3}, {%4,%5,%6,%7}, {%8,%9}, {%0,%1,%2,%3};"
                    : "+f"(acc[mi][nj*2+1][0]), "+f"(acc[mi][nj*2+1][1]),
                      "+f"(acc[mi][nj*2+1][2]), "+f"(acc[mi][nj*2+1][3])
                    : "r"(af[mi][0]), "r"(af[mi][1]), "r"(af[mi][2]), "r"(af[mi][3]),
                      "r"(r2), "r"(r3));
            }
        }
    }
    __syncthreads();   // inputs dead; reuse arena as output staging
    #pragma unroll
    for (int mi = 0; mi < 2; mi++)
        #pragma unroll
        for (int ni = 0; ni < 8; ni++) {
            int col = warp_n + ni*8 + (lid & 3)*2;
            int h_l = col >> 6, e = col & 63;
            int rl0 = warp_m + mi*16 + (lid >> 2);
            *(__half2*)&so[rl0 >> 3][h_l][(rl0 & 7)*64 + e] =
                __floats2half2_rn(acc[mi][ni][0], acc[mi][ni][1]);
            int rl1 = rl0 + 8;
            *(__half2*)&so[rl1 >> 3][h_l][(rl1 & 7)*64 + e] =
                __floats2half2_rn(acc[mi][ni][2], acc[mi][ni][3]);
        }
    __syncthreads();
    int b = rb >> 13, s0 = (rb >> 3) & 1023;
    int h0 = cb >> 6;
    #pragma unroll
    for (int i = 0; i < 8; i++) {
        int idx = tid + i*256;
        int row = idx >> 6, c = idx & 63;
        int s_l = row >> 1, h_l = row & 1;
        *(uint4*)&g_va[((size_t)((b*8 + h0 + h_l)*1024) + s0 + s_l)*512 + c*8] =
            *(const uint4*)&so[s_l][h_l][c*8];
    }
}

// ---------------- K4: fused flash attention ----------------
#define FLASH_SMEM 174080
#define TSTR 136
__global__ __launch_bounds__(256) void k_flash(const float* __restrict__ log_temp) {
    extern __shared__ __align__(16) __half fsm[];
    __half* qs = fsm;
    __half* ks = fsm + 17408;
    __half* vs = fsm + 17408*3;

    int tid = threadIdx.x, wid = tid >> 5, lid = tid & 31;
    int bh = blockIdx.z, b = bh >> 3, h = bh & 7;
    int qb = blockIdx.y * 128, nb = blockIdx.x * 128;
    const __half* Qg = g_qrff + ((size_t)bh*1024 + qb)*128;
    const __half* Kg = g_krff + (size_t)bh*1024*128;
    const __half* Vg = g_va   + (size_t)bh*1024*512 + nb;
    float temp = __expf(log_temp[h]);

    auto loadQ = [&]() {
        #pragma unroll
        for (int i = 0; i < 8; i++) {
            int id = tid + i*256;
            int r = id >> 4, c = id & 15;
            uint32_t d = s2u(qs + r*TSTR + c*8);
            asm volatile("cp.async.cg.shared.global [%0], [%1], 16;"
                         :: "r"(d), "l"(Qg + (size_t)r*128 + c*8));
        }
    };
    auto loadKV = [&](int st, int kt) {
        __half* kp = ks + st*17408;
        __half* vp = vs + st*17408;
        #pragma unroll
        for (int i = 0; i < 8; i++) {
            int id = tid + i*256;
            int r = id >> 4, c = id & 15;
            uint32_t d = s2u(kp + r*TSTR + c*8);
            asm volatile("cp.async.cg.shared.global [%0], [%1], 16;"
                         :: "r"(d), "l"(Kg + (size_t)(kt*128 + r)*128 + c*8));
        }
        #pragma unroll
        for (int i = 0; i < 8; i++) {
            int id = tid + i*256;
            int r = id >> 4, c = id & 15;
            uint32_t d = s2u(vp + r*TSTR + c*8);
            asm volatile("cp.async.cg.shared.global [%0], [%1], 16;"
                         :: "r"(d), "l"(Vg + (size_t)(kt*128 + r)*512 + c*8));
        }
        asm volatile("cp.async.commit_group;" ::: "memory");
    };

    loadQ(); loadKV(0, 0);
    loadKV(1, 1);

    float accO[16][4] = {};
    float m0 = -1e30f, m1 = -1e30f, l0 = 0.f, l1 = 0.f;

    for (int kt = 0; kt < 8; kt++) {
        int st = kt & 1;
        if (kt < 7) asm volatile("cp.async.wait_group 1;" ::: "memory");
        else        asm volatile("cp.async.wait_group 0;" ::: "memory");
        __syncthreads();

        float accS[16][4] = {};
        const __half* kp = ks + st*17408;
        #pragma unroll
        for (int kk = 0; kk < 8; kk++) {
            uint32_t af[4];
            {
                uint32_t addr = s2u(qs + (wid*16 + (lid & 15))*TSTR + kk*16 + ((lid >> 4) << 3));
                asm volatile("ldmatrix.sync.aligned.m8n8.x4.shared.b16 {%0,%1,%2,%3}, [%4];"
                    : "=r"(af[0]), "=r"(af[1]), "=r"(af[2]), "=r"(af[3]) : "r"(addr));
            }
            #pragma unroll
            for (int nj = 0; nj < 8; nj++) {
                uint32_t r0, r1, r2, r3;
                int n = nj*16 + ((lid >> 4) << 3) + (lid & 7);
                int k = kk*16 + (((lid >> 3) & 1) << 3);
                uint32_t addr = s2u(kp + n*TSTR + k);
                asm volatile("ldmatrix.sync.aligned.m8n8.x4.shared.b16 {%0,%1,%2,%3}, [%4];"
                    : "=r"(r0), "=r"(r1), "=r"(r2), "=r"(r3) : "r"(addr));
                asm volatile("mma.sync.aligned.m16n8k16.row.col.f32.f16.f16.f32 "
                    "{%0,%1,%2,%3}, {%4,%5,%6,%7}, {%8,%9}, {%0,%1,%2,%3};"
                    : "+f"(accS[nj*2][0]), "+f"(accS[nj*2][1]),
                      "+f"(accS[nj*2][2]), "+f"(accS[nj*2][3])
                    : "r"(af[0]), "r"(af[1]), "r"(af[2]), "r"(af[3]), "r"(r0), "r"(r1));
                asm volatile("mma.sync.aligned.m16n8k16.row.col.f32.f16.f16.f32 "
                    "{%0,%1,%2,%3}, {%4,%5,%6,%7}, {%8,%9}, {%0,%1,%2,%3};"
                    : "+f"(accS[nj*2+1][0]), "+f"(accS[nj*2+1][1]),
                      "+f"(accS[nj*2+1][2]), "+f"(accS[nj*2+1][3])
                    : "r"(af[0]), "r"(af[1]), "r"(af[2]), "r"(af[3]), "r"(r2), "r"(r3));
            }
        }

        float mx0 = -1e30f, mx1 = -1e30f;
        #pragma unroll
        for (int ni = 0; ni < 16; ni++) {
            accS[ni][0] *= temp; accS[ni][1] *= temp;
            accS[ni][2] *= temp; accS[ni][3] *= temp;
            mx0 = fmaxf(mx0, fmaxf(accS[ni][0], accS[ni][1]));
            mx1 = fmaxf(mx1, fmaxf(accS[ni][2], accS[ni][3]));
        }
        mx0 = fmaxf(mx0, __shfl_xor_sync(~0u, mx0, 1));
        mx0 = fmaxf(mx0, __shfl_xor_sync(~0u, mx0, 2));
        mx1 = fmaxf(mx1, __shfl_xor_sync(~0u, mx1, 1));
        mx1 = fmaxf(mx1, __shfl_xor_sync(~0u, mx1, 2));
        float mn0 = fmaxf(m0, mx0), mn1 = fmaxf(m1, mx1);
        float sf0 = __expf(m0 - mn0), sf1 = __expf(m1 - mn1);
        m0 = mn0; m1 = mn1;
        float s0 = 0.f, s1 = 0.f;
        uint32_t pf[16][2];
        #pragma unroll
        for (int ni = 0; ni < 16; ni++) {
            float p0 = __expf(accS[ni][0] - m0);
            float p1 = __expf(accS[ni][1] - m0);
            float p2 = __expf(accS[ni][2] - m1);
            float p3 = __expf(accS[ni][3] - m1);
            s0 += p0 + p1; s1 += p2 + p3;
            __half2 h01 = __floats2half2_rn(p0, p1);
            __half2 h23 = __floats2half2_rn(p2, p3);
            pf[ni][0] = *(uint32_t*)&h01;
            pf[ni][1] = *(uint32_t*)&h23;
        }
        s0 += __shfl_xor_sync(~0u, s0, 1); s0 += __shfl_xor_sync(~0u, s0, 2);
        s1 += __shfl_xor_sync(~0u, s1, 1); s1 += __shfl_xor_sync(~0u, s1, 2);
        l0 = l0*sf0 + s0; l1 = l1*sf1 + s1;
        #pragma unroll
        for (int n2 = 0; n2 < 16; n2++) {
            accO[n2][0] *= sf0; accO[n2][1] *= sf0;
            accO[n2][2] *= sf1; accO[n2][3] *= sf1;
        }

        const __half* vp = vs + st*17408;
        #pragma unroll
        for (int kk2 = 0; kk2 < 8; kk2++) {
            uint32_t a0 = pf[kk2*2][0],   a1 = pf[kk2*2][1];
            uint32_t a2 = pf[kk2*2+1][0], a3 = pf[kk2*2+1][1];
            #pragma unroll
            for (int n2p = 0; n2p < 8; n2p++) {
                uint32_t r0, r1, r2, r3;
                int krow = kk2*16 + (lid & 7) + (((lid >> 3) & 1) << 3);
                int ncol = n2p*16 + ((lid >> 4) << 3);
                uint32_t addr = s2u(vp + krow*TSTR + ncol);
                asm volatile("ldmatrix.sync.aligned.m8n8.x4.trans.shared.b16 {%0,%1,%2,%3}, [%4];"
                    : "=r"(r0), "=r"(r1), "=r"(r2), "=r"(r3) : "r"(addr));
                asm volatile("mma.sync.aligned.m16n8k16.row.col.f32.f16.f16.f32 "
                    "{%0,%1,%2,%3}, {%4,%5,%6,%7}, {%8,%9}, {%0,%1,%2,%3};"
                    : "+f"(accO[n2p*2][0]), "+f"(accO[n2p*2][1]),
                      "+f"(accO[n2p*2][2]), "+f"(accO[n2p*2][3])
                    : "r"(a0), "r"(a1), "r"(a2), "r"(a3), "r"(r0), "r"(r1));
                asm volatile("mma.sync.aligned.m16n8k16.row.col.f32.f16.f16.f32 "
                    "{%0,%1,%2,%3}, {%4,%5,%6,%7}, {%8,%9}, {%0,%1,%2,%3};"
                    : "+f"(accO[n2p*2+1][0]), "+f"(accO[n2p*2+1][1]),
                      "+f"(accO[n2p*2+1][2]), "+f"(accO[n2p*2+1][3])
                    : "r"(a0), "r"(a1), "r"(a2), "r"(a3), "r"(r2), "r"(r3));
            }
        }
        __syncthreads();
        if (kt + 2 < 8) loadKV(st, kt + 2);
    }

    // epilogue: normalize + write HALF in oproj layout [(b,q,m)][(h,e)]
    float inv0 = 1.0f / l0, inv1 = 1.0f / l1;
    int q0 = qb + wid*16 + (lid >> 2);
    int q1 = q0 + 8;
    #pragma unroll
    for (int n2 = 0; n2 < 16; n2++) {
        int col = nb + n2*8 + (lid & 3)*2;
        int m = col >> 6, e = col & 63;
        __half* p0 = g_outh + ((size_t)(b*1024 + q0)*8 + m)*512 + h*64 + e;
        __half* p1 = g_outh + ((size_t)(b*1024 + q1)*8 + m)*512 + h*64 + e;
        *(__half2*)p0 = __floats2half2_rn(accO[n2][0]*inv0, accO[n2][1]*inv0);
        *(__half2*)p1 = __floats2half2_rn(accO[n2][2]*inv1, accO[n2][3]*inv1);
    }
}

// ---------------- K7: output projection via HMMA (M=32768, N=64, K=512) -----
__global__ __launch_bounds__(256) void k_oproj2(float* __restrict__ out_atoms) {
    __shared__ __align__(16) __half sA[2][128][40];
    __shared__ __align__(16) __half sB[2][64][40];
    int tid = threadIdx.x, wid = tid >> 5, lid = tid & 31;
    int rb = blockIdx.x * 128;
    int warp_m = (wid & 3) * 32, warp_n = (wid >> 2) * 32;
    float acc[2][4][4] = {};

    auto load = [&](int st, int kc) {
        #pragma unroll
        for (int i = 0; i < 2; i++) {
            int id = tid + i*256;          // 0..511
            int r = id >> 2, c = id & 3;
            uint32_t d = s2u(&sA[st][r][c*8]);
            asm volatile("cp.async.cg.shared.global [%0], [%1], 16;"
                         :: "r"(d), "l"(g_outh + (size_t)(rb + r)*512 + kc + c*8));
        }
        {
            int r = tid >> 2, c = tid & 3;
            uint32_t d = s2u(&sB[st][r][c*8]);
            asm volatile("cp.async.cg.shared.global [%0], [%1], 16;"
                         :: "r"(d), "l"(g_Woh + (size_t)r*512 + kc + c*8));
        }
        asm volatile("cp.async.commit_group;" ::: "memory");
    };

    load(0, 0);
    load(1, 32);

    for (int c = 0; c < 16; c++) {
        int st = c & 1;
        if (c < 14) asm volatile("cp.async.wait_group 1;" ::: "memory");
        else        asm volatile("cp.async.wait_group 0;" ::: "memory");
        __syncthreads();

        #pragma unroll
        for (int kk = 0; kk < 32; kk += 16) {
            uint32_t af[2][4];
            #pragma unroll
            for (int mi = 0; mi < 2; mi++) {
                uint32_t addr = s2u(&sA[st][warp_m + mi*16 + (lid & 15)][kk + ((lid >> 4) << 3)]);
                asm volatile("ldmatrix.sync.aligned.m8n8.x4.shared.b16 {%0,%1,%2,%3}, [%4];"
                    : "=r"(af[mi][0]), "=r"(af[mi][1]), "=r"(af[mi][2]), "=r"(af[mi][3])
                    : "r"(addr));
            }
            #pragma unroll
            for (int nj = 0; nj < 2; nj++) {
                uint32_t r0, r1, r2, r3;
                int n = warp_n + nj*16 + ((lid >> 4) << 3) + (lid & 7);
                int k = kk + (((lid >> 3) & 1) << 3);
                uint32_t addr = s2u(&sB[st][n][k]);
                asm volatile("ldmatrix.sync.aligned.m8n8.x4.shared.b16 {%0,%1,%2,%3}, [%4];"
                    : "=r"(r0), "=r"(r1), "=r"(r2), "=r"(r3) : "r"(addr));
                #pragma unroll
                for (int mi = 0; mi < 2; mi++) {
                    asm volatile("mma.sync.aligned.m16n8k16.row.col.f32.f16.f16.f32 "
                        "{%0,%1,%2,%3}, {%4,%5,%6,%7}, {%8,%9}, {%0,%1,%2,%3};"
                        : "+f"(acc[mi][nj*2][0]), "+f"(acc[mi][nj*2][1]),
                          "+f"(acc[mi][nj*2][2]), "+f"(acc[mi][nj*2][3])
                        : "r"(af[mi][0]), "r"(af[mi][1]), "r"(af[mi][2]), "r"(af[mi][3]),
                          "r"(r0), "r"(r1));
                    asm volatile("mma.sync.aligned.m16n8k16.row.col.f32.f16.f16.f32 "
                        "{%0,%1,%2,%3}, {%4,%5,%6,%7}, {%8,%9}, {%0,%1,%2,%3};"
                        : "+f"(acc[mi][nj*2+1][0]), "+f"(acc[mi][nj*2+1][1]),
                          "+f"(acc[mi][nj*2+1][2]), "+f"(acc[mi][nj*2+1][3])
                        : "r"(af[mi][0]), "r"(af[mi][1]), "r"(af[mi][2]), "r"(af[mi][3]),
                          "r"(r2), "r"(r3));
                }
            }
        }
        __syncthreads();
        if (c + 2 < 16) load(st, (c + 2)*32);
    }

    #pragma unroll
    for (int mi = 0; mi < 2; mi++)
        #pragma unroll
        for (int ni = 0; ni < 4; ni++) {
            int row = rb + warp_m + mi*16 + (lid >> 2);
            int col = warp_n + ni*8 + (lid & 3)*2;
            float* Cp = out_atoms + (size_t)row*64 + col;
            Cp[0]       = acc[mi][ni][0];
            Cp[1]       = acc[mi][ni][1];
            Cp[64*8]    = acc[mi][ni][2];
            Cp[64*8 + 1]= acc[mi][ni][3];
        }
}

// ---------------- K8: log-weight update ----------------
__global__ __launch_bounds__(64) void k_lw(const float* __restrict__ Ww,
                                           const float* __restrict__ qlw,
                                           const float* __restrict__ out_atoms,
                                           float* __restrict__ out2) {
    __shared__ float mean[64];
    int bq = blockIdx.x;
    int t = threadIdx.x;
    float s = 0.f;
    #pragma unroll
    for (int m = 0; m < 8; m++)
        s += out_atoms[(size_t)(bq*8 + m)*64 + t];
    mean[t] = s * 0.125f;
    __syncthreads();
    if (t < 8) {
        float acc = 0.f;
        #pragma unroll
        for (int d = 0; d < 64; d++)
            acc = fmaf(mean[d], Ww[t*64 + d], acc);
        out2[bq*8 + t] = qlw[bq*8 + t] + acc;
    }
}

// ---------------- launch ----------------
extern "C" void kernel_launch(void* const* d_in, const int* in_sizes, int n_in,
                              void* d_out, int out_size) {
    const float* q_atoms   = (const float*)d_in[0];
    const float* q_weights = (const float*)d_in[1];
    const float* q_logw    = (const float*)d_in[2];
    const float* k_atoms   = (const float*)d_in[3];
    const float* k_weights = (const float*)d_in[4];
    const float* v_atoms   = (const float*)d_in[5];
    const float* Wq        = (const float*)d_in[6];
    const float* Wk        = (const float*)d_in[7];
    const float* Wv        = (const float*)d_in[8];
    const float* Wo        = (const float*)d_in[9];
    const float* Ww        = (const float*)d_in[10];
    const float* log_bw    = (const float*)d_in[11];
    const float* log_temp  = (const float*)d_in[12];
    const float* rff_base  = (const float*)d_in[13];

    float* out_atoms = (float*)d_out;
    float* out_lw    = (float*)d_out + (size_t)B_*SQ_*M_*D_;

    cudaFuncSetAttribute(k_flash, cudaFuncAttributeMaxDynamicSharedMemorySize, FLASH_SMEM);

    k_combine<<<H_, 256>>>(Wq, Wk, rff_base, log_bw);
    k_cvt<<<2048, 256>>>(v_atoms, Wv, Wo);
    k_rff<<<dim3(SQ_/16,  BH_), 256>>>(q_atoms, q_weights, 1);
    k_rff<<<dim3(SKV_/16, BH_), 256>>>(k_atoms, k_weights, 0);
    k_va2<<<dim3(4, 256), 256>>>();
    k_flash<<<dim3(4, 8, BH_), 256, FLASH_SMEM>>>(log_temp);
    k_oproj2<<<256, 256>>>(out_atoms);
    k_lw<<<B_*SQ_, 64>>>(Ww, q_logw, out_atoms, out_lw);
}

// round 13
// speedup vs baseline: 3.3217x; 1.0575x over previous
#include <cuda_runtime.h>
#include <cuda_fp16.h>
#include <cstdint>
#include <math.h>

#define B_   4
#define SQ_  1024
#define SKV_ 1024
#define M_   8
#define D_   64
#define H_   8
#define F_   64
#define BH_  (B_*H_)

// ---------------- scratch (device globals; no allocation) ----------------
__device__ float  g_Wqf[H_*D_*F_];
__device__ float  g_Wkf[H_*D_*F_];
__device__ __half g_qrff[(size_t)BH_*SQ_*2*F_];      // [bh][q][128]
__device__ __half g_krff[(size_t)BH_*SKV_*2*F_];     // [bh][k][128]
__device__ __half g_vah [(size_t)B_*SKV_*M_*D_];     // v_atoms in half (row-major)
__device__ __half g_Wvh [512*64];
__device__ __half g_Woh [64*512];
__device__ __half g_va  [(size_t)BH_*SKV_*512];      // [bh][s][m*64+e]
__device__ __half g_outh[(size_t)BH_*SQ_*M_*D_];     // [(b,q,m)][(h,e)] half

__device__ __forceinline__ uint32_t s2u(const void* p) {
    uint32_t a;
    asm("{ .reg .u64 t; cvta.to.shared.u64 t, %1; cvt.u32.u64 %0, t; }" : "=r"(a) : "l"(p));
    return a;
}

// ---------------- K0: convert v_atoms / Wv / Wo to half ----------------
__global__ __launch_bounds__(256) void k_cvt(const float* __restrict__ va,
                                             const float* __restrict__ Wv,
                                             const float* __restrict__ Wo) {
    int i = blockIdx.x*256 + threadIdx.x;          // grid 2048 -> i < 524288
    float4 v = *(const float4*)&va[(size_t)i*4];
    __half2 h0 = __floats2half2_rn(v.x, v.y), h1 = __floats2half2_rn(v.z, v.w);
    uint2 pk; pk.x = *(uint32_t*)&h0; pk.y = *(uint32_t*)&h1;
    *(uint2*)&g_vah[(size_t)i*4] = pk;
    if (i < 8192) {
        float4 a = *(const float4*)&Wv[i*4];
        __half2 a0 = __floats2half2_rn(a.x, a.y), a1 = __floats2half2_rn(a.z, a.w);
        uint2 p2; p2.x = *(uint32_t*)&a0; p2.y = *(uint32_t*)&a1;
        *(uint2*)&g_Wvh[i*4] = p2;
        float4 b = *(const float4*)&Wo[i*4];
        __half2 b0 = __floats2half2_rn(b.x, b.y), b1 = __floats2half2_rn(b.z, b.w);
        uint2 p3; p3.x = *(uint32_t*)&b0; p3.y = *(uint32_t*)&b1;
        *(uint2*)&g_Woh[i*4] = p3;
    }
}

// ---------------- K1: combined projection-RFF matrices ----------------
__global__ __launch_bounds__(256) void k_combine(const float* __restrict__ Wq,
                                                 const float* __restrict__ Wk,
                                                 const float* __restrict__ base,
                                                 const float* __restrict__ log_bw) {
    __shared__ float sWq[64*64], sWk[64*64], sB[64*64];
    int h = blockIdx.x;
    float inv = expf(-log_bw[h]);
    for (int i = threadIdx.x; i < 4096; i += 256) {
        sWq[i] = Wq[h*4096 + i];
        sWk[i] = Wk[h*4096 + i];
        sB[i]  = base[h*4096 + i] * inv;
    }
    __syncthreads();
    for (int idx = threadIdx.x; idx < 4096; idx += 256) {
        int d = idx >> 6, f = idx & 63;
        float aq = 0.f, ak = 0.f;
        #pragma unroll
        for (int e = 0; e < 64; e++) {
            float bf = sB[e*64 + f];
            aq = fmaf(sWq[e*64 + d], bf, aq);
            ak = fmaf(sWk[e*64 + d], bf, ak);
        }
        g_Wqf[h*4096 + d*64 + f] = aq;
        g_Wkf[h*4096 + d*64 + f] = ak;
    }
}

// ---------------- K2: fused projection + RFF encode, f-blocked x2 ----------
// 256 threads = 8 s-lanes x 32 f-lanes; each thread computes f = fl and fl+32.
__global__ __launch_bounds__(256) void k_rff(const float* __restrict__ atoms,
                                             const float* __restrict__ weights,
                                             int is_q) {
    __shared__ float sWT[64*68];                    // [f][d], pad 68
    __shared__ __align__(16) float sAt[8][8][64];   // [sl][m][d]
    __shared__ float sw[8][8];
    int bh = blockIdx.y;
    int b = bh >> 3, h = bh & 7;
    const float* Wf = is_q ? g_Wqf : g_Wkf;
    __half* dstbase = (is_q ? g_qrff : g_krff);
    for (int i = threadIdx.x; i < 4096; i += 256) {
        int d = i >> 6, f = i & 63;
        sWT[f*68 + d] = Wf[h*4096 + i];
    }
    int s0 = blockIdx.x * 16;
    int fl = threadIdx.x & 31;
    int sl = threadIdx.x >> 5;
    for (int ss = 0; ss < 16; ss += 8) {
        __syncthreads();
        for (int i = threadIdx.x; i < 4096; i += 256) {
            int si = i >> 9;          // 0..7
            int md = i & 511;
            sAt[si][md >> 6][md & 63] =
                atoms[(size_t)(b*1024 + s0 + ss + si)*512 + md];
        }
        if (threadIdx.x < 64) {
            int si = threadIdx.x >> 3, m = threadIdx.x & 7;
            sw[si][m] = weights[(b*1024 + s0 + ss + si)*8 + m];
        }
        __syncthreads();
        float p0[8], p1[8];
        #pragma unroll
        for (int m = 0; m < 8; m++) { p0[m] = 0.f; p1[m] = 0.f; }
        #pragma unroll
        for (int dq = 0; dq < 64; dq += 4) {
            float4 w0 = *(const float4*)&sWT[fl*68 + dq];
            float4 w1 = *(const float4*)&sWT[(fl + 32)*68 + dq];
            #pragma unroll
            for (int m = 0; m < 8; m++) {
                float4 av = *(const float4*)&sAt[sl][m][dq];
                p0[m] = fmaf(av.x, w0.x, p0[m]);
                p0[m] = fmaf(av.y, w0.y, p0[m]);
                p0[m] = fmaf(av.z, w0.z, p0[m]);
                p0[m] = fmaf(av.w, w0.w, p0[m]);
                p1[m] = fmaf(av.x, w1.x, p1[m]);
                p1[m] = fmaf(av.y, w1.y, p1[m]);
                p1[m] = fmaf(av.z, w1.z, p1[m]);
                p1[m] = fmaf(av.w, w1.w, p1[m]);
            }
        }
        float ac0 = 0.f, as0 = 0.f, ac1 = 0.f, as1 = 0.f;
        #pragma unroll
        for (int m = 0; m < 8; m++) {
            float w = sw[sl][m];
            float sv, cv;
            __sincosf(p0[m], &sv, &cv);
            ac0 = fmaf(w, cv, ac0); as0 = fmaf(w, sv, as0);
            __sincosf(p1[m], &sv, &cv);
            ac1 = fmaf(w, cv, ac1); as1 = fmaf(w, sv, as1);
        }
        int s = s0 + ss + sl;
        __half* dst = dstbase + ((size_t)bh*1024 + s)*128;
        dst[fl]           = __float2half(ac0 * 0.125f);
        dst[fl + 32]      = __float2half(ac1 * 0.125f);
        dst[64 + fl]      = __float2half(as0 * 0.125f);
        dst[96 + fl]      = __float2half(as1 * 0.125f);
    }
}

// ---------------- K3: va projection via HMMA (M=32768, N=512, K=64) ----------
__global__ __launch_bounds__(256) void k_va2() {
    __shared__ __align__(16) char sraw[36864];
    __half (*sA)[72] = (__half (*)[72])sraw;                 // [128][72]
    __half (*sB)[72] = (__half (*)[72])(sraw + 18432);       // [128][72]
    __half (*so)[2][512] = (__half (*)[2][512])sraw;         // aliased staging

    int tid = threadIdx.x, wid = tid >> 5, lid = tid & 31;
    int cb = blockIdx.x * 128, rb = blockIdx.y * 128;
    int warp_m = (wid & 3) * 32, warp_n = (wid >> 2) * 64;

    #pragma unroll
    for (int i = 0; i < 4; i++) {
        int id = tid + i*256;
        int r = id >> 3, c = id & 7;
        uint32_t d = s2u(&sA[r][c*8]);
        asm volatile("cp.async.cg.shared.global [%0], [%1], 16;"
                     :: "r"(d), "l"(g_vah + (size_t)(rb + r)*64 + c*8));
    }
    #pragma unroll
    for (int i = 0; i < 4; i++) {
        int id = tid + i*256;
        int r = id >> 3, c = id & 7;
        uint32_t d = s2u(&sB[r][c*8]);
        asm volatile("cp.async.cg.shared.global [%0], [%1], 16;"
                     :: "r"(d), "l"(g_Wvh + (size_t)(cb + r)*64 + c*8));
    }
    asm volatile("cp.async.commit_group;" ::: "memory");
    asm volatile("cp.async.wait_group 0;" ::: "memory");
    __syncthreads();

    float acc[2][8][4] = {};
    #pragma unroll
    for (int kk = 0; kk < 4; kk++) {
        uint32_t af[2][4];
        #pragma unroll
        for (int mi = 0; mi < 2; mi++) {
            uint32_t addr = s2u(&sA[warp_m + mi*16 + (lid & 15)][kk*16 + ((lid >> 4) << 3)]);
            asm volatile("ldmatrix.sync.aligned.m8n8.x4.shared.b16 {%0,%1,%2,%3}, [%4];"
                : "=r"(af[mi][0]), "=r"(af[mi][1]), "=r"(af[mi][2]), "=r"(af[mi][3])
                : "r"(addr));
        }
        #pragma unroll
        for (int nj = 0; nj < 4; nj++) {
            uint32_t r0, r1, r2, r3;
            int n = warp_n + nj*16 + ((lid >> 4) << 3) + (lid & 7);
            int k = kk*16 + (((lid >> 3) & 1) << 3);
            uint32_t addr = s2u(&sB[n][k]);
            asm volatile("ldmatrix.sync.aligned.m8n8.x4.shared.b16 {%0,%1,%2,%3}, [%4];"
                : "=r"(r0), "=r"(r1), "=r"(r2), "=r"(r3) : "r"(addr));
            #pragma unroll
            for (int mi = 0; mi < 2; mi++) {
                asm volatile("mma.sync.aligned.m16n8k16.row.col.f32.f16.f16.f32 "
                    "{%0,%1,%2,%3}, {%4,%5,%6,%7}, {%8,%9}, {%0,%1,%2,%3};"
                    : "+f"(acc[mi][nj*2][0]), "+f"(acc[mi][nj*2][1]),
                      "+f"(acc[mi][nj*2][2]), "+f"(acc[mi][nj*2][3])
                    : "r"(af[mi][0]), "r"(af[mi][1]), "r"(af[mi][2]), "r"(af[mi][3]),
                      "r"(r0), "r"(r1));
                asm volatile("mma.sync.aligned.m16n8k16.row.col.f32.f16.f16.f32 "
                    "{%0,%1,%2,%3}, {%4,%5,%6,%7}, {%8,%9}, {%0,%1,%2,%3};"
                    : "+f"(acc[mi][nj*2+1][0]), "+f"(acc[mi][nj*2+1][1]),
                      "+f"(acc[mi][nj*2+1][2]), "+f"(acc[mi][nj*2+1][3])
                    : "r"(af[mi][0]), "r"(af[mi][1]), "r"(af[mi][2]), "r"(af[mi][3]),
                      "r"(r2), "r"(r3));
            }
        }
    }
    __syncthreads();   // inputs dead; reuse arena as output staging
    #pragma unroll
    for (int mi = 0; mi < 2; mi++)
        #pragma unroll
        for (int ni = 0; ni < 8; ni++) {
            int col = warp_n + ni*8 + (lid & 3)*2;
            int h_l = col >> 6, e = col & 63;
            int rl0 = warp_m + mi*16 + (lid >> 2);
            *(__half2*)&so[rl0 >> 3][h_l][(rl0 & 7)*64 + e] =
                __floats2half2_rn(acc[mi][ni][0], acc[mi][ni][1]);
            int rl1 = rl0 + 8;
            *(__half2*)&so[rl1 >> 3][h_l][(rl1 & 7)*64 + e] =
                __floats2half2_rn(acc[mi][ni][2], acc[mi][ni][3]);
        }
    __syncthreads();
    int b = rb >> 13, s0 = (rb >> 3) & 1023;
    int h0 = cb >> 6;
    #pragma unroll
    for (int i = 0; i < 8; i++) {
        int idx = tid + i*256;
        int row = idx >> 6, c = idx & 63;
        int s_l = row >> 1, h_l = row & 1;
        *(uint4*)&g_va[((size_t)((b*8 + h0 + h_l)*1024) + s0 + s_l)*512 + c*8] =
            *(const uint4*)&so[s_l][h_l][c*8];
    }
}

// ---------------- K4: fused flash attention ----------------
#define FLASH_SMEM 174080
#define TSTR 136
__global__ __launch_bounds__(256) void k_flash(const float* __restrict__ log_temp) {
    extern __shared__ __align__(16) __half fsm[];
    __half* qs = fsm;
    __half* ks = fsm + 17408;
    __half* vs = fsm + 17408*3;

    int tid = threadIdx.x, wid = tid >> 5, lid = tid & 31;
    int bh = blockIdx.z, b = bh >> 3, h = bh & 7;
    int qb = blockIdx.y * 128, nb = blockIdx.x * 128;
    const __half* Qg = g_qrff + ((size_t)bh*1024 + qb)*128;
    const __half* Kg = g_krff + (size_t)bh*1024*128;
    const __half* Vg = g_va   + (size_t)bh*1024*512 + nb;
    float temp = __expf(log_temp[h]);

    auto loadQ = [&]() {
        #pragma unroll
        for (int i = 0; i < 8; i++) {
            int id = tid + i*256;
            int r = id >> 4, c = id & 15;
            uint32_t d = s2u(qs + r*TSTR + c*8);
            asm volatile("cp.async.cg.shared.global [%0], [%1], 16;"
                         :: "r"(d), "l"(Qg + (size_t)r*128 + c*8));
        }
    };
    auto loadKV = [&](int st, int kt) {
        __half* kp = ks + st*17408;
        __half* vp = vs + st*17408;
        #pragma unroll
        for (int i = 0; i < 8; i++) {
            int id = tid + i*256;
            int r = id >> 4, c = id & 15;
            uint32_t d = s2u(kp + r*TSTR + c*8);
            asm volatile("cp.async.cg.shared.global [%0], [%1], 16;"
                         :: "r"(d), "l"(Kg + (size_t)(kt*128 + r)*128 + c*8));
        }
        #pragma unroll
        for (int i = 0; i < 8; i++) {
            int id = tid + i*256;
            int r = id >> 4, c = id & 15;
            uint32_t d = s2u(vp + r*TSTR + c*8);
            asm volatile("cp.async.cg.shared.global [%0], [%1], 16;"
                         :: "r"(d), "l"(Vg + (size_t)(kt*128 + r)*512 + c*8));
        }
        asm volatile("cp.async.commit_group;" ::: "memory");
    };

    loadQ(); loadKV(0, 0);
    loadKV(1, 1);

    float accO[16][4] = {};
    float m0 = -1e30f, m1 = -1e30f, l0 = 0.f, l1 = 0.f;

    for (int kt = 0; kt < 8; kt++) {
        int st = kt & 1;
        if (kt < 7) asm volatile("cp.async.wait_group 1;" ::: "memory");
        else        asm volatile("cp.async.wait_group 0;" ::: "memory");
        __syncthreads();

        float accS[16][4] = {};
        const __half* kp = ks + st*17408;
        #pragma unroll
        for (int kk = 0; kk < 8; kk++) {
            uint32_t af[4];
            {
                uint32_t addr = s2u(qs + (wid*16 + (lid & 15))*TSTR + kk*16 + ((lid >> 4) << 3));
                asm volatile("ldmatrix.sync.aligned.m8n8.x4.shared.b16 {%0,%1,%2,%3}, [%4];"
                    : "=r"(af[0]), "=r"(af[1]), "=r"(af[2]), "=r"(af[3]) : "r"(addr));
            }
            #pragma unroll
            for (int nj = 0; nj < 8; nj++) {
                uint32_t r0, r1, r2, r3;
                int n = nj*16 + ((lid >> 4) << 3) + (lid & 7);
                int k = kk*16 + (((lid >> 3) & 1) << 3);
                uint32_t addr = s2u(kp + n*TSTR + k);
                asm volatile("ldmatrix.sync.aligned.m8n8.x4.shared.b16 {%0,%1,%2,%3}, [%4];"
                    : "=r"(r0), "=r"(r1), "=r"(r2), "=r"(r3) : "r"(addr));
                asm volatile("mma.sync.aligned.m16n8k16.row.col.f32.f16.f16.f32 "
                    "{%0,%1,%2,%3}, {%4,%5,%6,%7}, {%8,%9}, {%0,%1,%2,%3};"
                    : "+f"(accS[nj*2][0]), "+f"(accS[nj*2][1]),
                      "+f"(accS[nj*2][2]), "+f"(accS[nj*2][3])
                    : "r"(af[0]), "r"(af[1]), "r"(af[2]), "r"(af[3]), "r"(r0), "r"(r1));
                asm volatile("mma.sync.aligned.m16n8k16.row.col.f32.f16.f16.f32 "
                    "{%0,%1,%2,%3}, {%4,%5,%6,%7}, {%8,%9}, {%0,%1,%2,%3};"
                    : "+f"(accS[nj*2+1][0]), "+f"(accS[nj*2+1][1]),
                      "+f"(accS[nj*2+1][2]), "+f"(accS[nj*2+1][3])
                    : "r"(af[0]), "r"(af[1]), "r"(af[2]), "r"(af[3]), "r"(r2), "r"(r3));
            }
        }

        float mx0 = -1e30f, mx1 = -1e30f;
        #pragma unroll
        for (int ni = 0; ni < 16; ni++) {
            accS[ni][0] *= temp; accS[ni][1] *= temp;
            accS[ni][2] *= temp; accS[ni][3] *= temp;
            mx0 = fmaxf(mx0, fmaxf(accS[ni][0], accS[ni][1]));
            mx1 = fmaxf(mx1, fmaxf(accS[ni][2], accS[ni][3]));
        }
        mx0 = fmaxf(mx0, __shfl_xor_sync(~0u, mx0, 1));
        mx0 = fmaxf(mx0, __shfl_xor_sync(~0u, mx0, 2));
        mx1 = fmaxf(mx1, __shfl_xor_sync(~0u, mx1, 1));
        mx1 = fmaxf(mx1, __shfl_xor_sync(~0u, mx1, 2));
        float mn0 = fmaxf(m0, mx0), mn1 = fmaxf(m1, mx1);
        float sf0 = __expf(m0 - mn0), sf1 = __expf(m1 - mn1);
        m0 = mn0; m1 = mn1;
        float s0 = 0.f, s1 = 0.f;
        uint32_t pf[16][2];
        #pragma unroll
        for (int ni = 0; ni < 16; ni++) {
            float p0 = __expf(accS[ni][0] - m0);
            float p1 = __expf(accS[ni][1] - m0);
            float p2 = __expf(accS[ni][2] - m1);
            float p3 = __expf(accS[ni][3] - m1);
            s0 += p0 + p1; s1 += p2 + p3;
            __half2 h01 = __floats2half2_rn(p0, p1);
            __half2 h23 = __floats2half2_rn(p2, p3);
            pf[ni][0] = *(uint32_t*)&h01;
            pf[ni][1] = *(uint32_t*)&h23;
        }
        s0 += __shfl_xor_sync(~0u, s0, 1); s0 += __shfl_xor_sync(~0u, s0, 2);
        s1 += __shfl_xor_sync(~0u, s1, 1); s1 += __shfl_xor_sync(~0u, s1, 2);
        l0 = l0*sf0 + s0; l1 = l1*sf1 + s1;
        #pragma unroll
        for (int n2 = 0; n2 < 16; n2++) {
            accO[n2][0] *= sf0; accO[n2][1] *= sf0;
            accO[n2][2] *= sf1; accO[n2][3] *= sf1;
        }

        const __half* vp = vs + st*17408;
        #pragma unroll
        for (int kk2 = 0; kk2 < 8; kk2++) {
            uint32_t a0 = pf[kk2*2][0],   a1 = pf[kk2*2][1];
            uint32_t a2 = pf[kk2*2+1][0], a3 = pf[kk2*2+1][1];
            #pragma unroll
            for (int n2p = 0; n2p < 8; n2p++) {
                uint32_t r0, r1, r2, r3;
                int krow = kk2*16 + (lid & 7) + (((lid >> 3) & 1) << 3);
                int ncol = n2p*16 + ((lid >> 4) << 3);
                uint32_t addr = s2u(vp + krow*TSTR + ncol);
                asm volatile("ldmatrix.sync.aligned.m8n8.x4.trans.shared.b16 {%0,%1,%2,%3}, [%4];"
                    : "=r"(r0), "=r"(r1), "=r"(r2), "=r"(r3) : "r"(addr));
                asm volatile("mma.sync.aligned.m16n8k16.row.col.f32.f16.f16.f32 "
                    "{%0,%1,%2,%3}, {%4,%5,%6,%7}, {%8,%9}, {%0,%1,%2,%3};"
                    : "+f"(accO[n2p*2][0]), "+f"(accO[n2p*2][1]),
                      "+f"(accO[n2p*2][2]), "+f"(accO[n2p*2][3])
                    : "r"(a0), "r"(a1), "r"(a2), "r"(a3), "r"(r0), "r"(r1));
                asm volatile("mma.sync.aligned.m16n8k16.row.col.f32.f16.f16.f32 "
                    "{%0,%1,%2,%3}, {%4,%5,%6,%7}, {%8,%9}, {%0,%1,%2,%3};"
                    : "+f"(accO[n2p*2+1][0]), "+f"(accO[n2p*2+1][1]),
                      "+f"(accO[n2p*2+1][2]), "+f"(accO[n2p*2+1][3])
                    : "r"(a0), "r"(a1), "r"(a2), "r"(a3), "r"(r2), "r"(r3));
            }
        }
        __syncthreads();
        if (kt + 2 < 8) loadKV(st, kt + 2);
    }

    // epilogue: normalize + write HALF in oproj layout [(b,q,m)][(h,e)]
    float inv0 = 1.0f / l0, inv1 = 1.0f / l1;
    int q0 = qb + wid*16 + (lid >> 2);
    int q1 = q0 + 8;
    #pragma unroll
    for (int n2 = 0; n2 < 16; n2++) {
        int col = nb + n2*8 + (lid & 3)*2;
        int m = col >> 6, e = col & 63;
        __half* p0 = g_outh + ((size_t)(b*1024 + q0)*8 + m)*512 + h*64 + e;
        __half* p1 = g_outh + ((size_t)(b*1024 + q1)*8 + m)*512 + h*64 + e;
        *(__half2*)p0 = __floats2half2_rn(accO[n2][0]*inv0, accO[n2][1]*inv0);
        *(__half2*)p1 = __floats2half2_rn(accO[n2][2]*inv1, accO[n2][3]*inv1);
    }
}

// ---------------- K7: output projection via HMMA (M=32768, N=64, K=512) -----
__global__ __launch_bounds__(256) void k_oproj2(float* __restrict__ out_atoms) {
    __shared__ __align__(16) __half sA[2][128][40];
    __shared__ __align__(16) __half sB[2][64][40];
    int tid = threadIdx.x, wid = tid >> 5, lid = tid & 31;
    int rb = blockIdx.x * 128;
    int warp_m = (wid & 3) * 32, warp_n = (wid >> 2) * 32;
    float acc[2][4][4] = {};

    auto load = [&](int st, int kc) {
        #pragma unroll
        for (int i = 0; i < 2; i++) {
            int id = tid + i*256;
            int r = id >> 2, c = id & 3;
            uint32_t d = s2u(&sA[st][r][c*8]);
            asm volatile("cp.async.cg.shared.global [%0], [%1], 16;"
                         :: "r"(d), "l"(g_outh + (size_t)(rb + r)*512 + kc + c*8));
        }
        {
            int r = tid >> 2, c = tid & 3;
            uint32_t d = s2u(&sB[st][r][c*8]);
            asm volatile("cp.async.cg.shared.global [%0], [%1], 16;"
                         :: "r"(d), "l"(g_Woh + (size_t)r*512 + kc + c*8));
        }
        asm volatile("cp.async.commit_group;" ::: "memory");
    };

    load(0, 0);
    load(1, 32);

    for (int c = 0; c < 16; c++) {
        int st = c & 1;
        if (c < 14) asm volatile("cp.async.wait_group 1;" ::: "memory");
        else        asm volatile("cp.async.wait_group 0;" ::: "memory");
        __syncthreads();

        #pragma unroll
        for (int kk = 0; kk < 32; kk += 16) {
            uint32_t af[2][4];
            #pragma unroll
            for (int mi = 0; mi < 2; mi++) {
                uint32_t addr = s2u(&sA[st][warp_m + mi*16 + (lid & 15)][kk + ((lid >> 4) << 3)]);
                asm volatile("ldmatrix.sync.aligned.m8n8.x4.shared.b16 {%0,%1,%2,%3}, [%4];"
                    : "=r"(af[mi][0]), "=r"(af[mi][1]), "=r"(af[mi][2]), "=r"(af[mi][3])
                    : "r"(addr));
            }
            #pragma unroll
            for (int nj = 0; nj < 2; nj++) {
                uint32_t r0, r1, r2, r3;
                int n = warp_n + nj*16 + ((lid >> 4) << 3) + (lid & 7);
                int k = kk + (((lid >> 3) & 1) << 3);
                uint32_t addr = s2u(&sB[st][n][k]);
                asm volatile("ldmatrix.sync.aligned.m8n8.x4.shared.b16 {%0,%1,%2,%3}, [%4];"
                    : "=r"(r0), "=r"(r1), "=r"(r2), "=r"(r3) : "r"(addr));
                #pragma unroll
                for (int mi = 0; mi < 2; mi++) {
                    asm volatile("mma.sync.aligned.m16n8k16.row.col.f32.f16.f16.f32 "
                        "{%0,%1,%2,%3}, {%4,%5,%6,%7}, {%8,%9}, {%0,%1,%2,%3};"
                        : "+f"(acc[mi][nj*2][0]), "+f"(acc[mi][nj*2][1]),
                          "+f"(acc[mi][nj*2][2]), "+f"(acc[mi][nj*2][3])
                        : "r"(af[mi][0]), "r"(af[mi][1]), "r"(af[mi][2]), "r"(af[mi][3]),
                          "r"(r0), "r"(r1));
                    asm volatile("mma.sync.aligned.m16n8k16.row.col.f32.f16.f16.f32 "
                        "{%0,%1,%2,%3}, {%4,%5,%6,%7}, {%8,%9}, {%0,%1,%2,%3};"
                        : "+f"(acc[mi][nj*2+1][0]), "+f"(acc[mi][nj*2+1][1]),
                          "+f"(acc[mi][nj*2+1][2]), "+f"(acc[mi][nj*2+1][3])
                        : "r"(af[mi][0]), "r"(af[mi][1]), "r"(af[mi][2]), "r"(af[mi][3]),
                          "r"(r2), "r"(r3));
                }
            }
        }
        __syncthreads();
        if (c + 2 < 16) load(st, (c + 2)*32);
    }

    #pragma unroll
    for (int mi = 0; mi < 2; mi++)
        #pragma unroll
        for (int ni = 0; ni < 4; ni++) {
            int row = rb + warp_m + mi*16 + (lid >> 2);
            int col = warp_n + ni*8 + (lid & 3)*2;
            float* Cp = out_atoms + (size_t)row*64 + col;
            Cp[0]       = acc[mi][ni][0];
            Cp[1]       = acc[mi][ni][1];
            Cp[64*8]    = acc[mi][ni][2];
            Cp[64*8 + 1]= acc[mi][ni][3];
        }
}

// ---------------- K8: log-weight update ----------------
__global__ __launch_bounds__(64) void k_lw(const float* __restrict__ Ww,
                                           const float* __restrict__ qlw,
                                           const float* __restrict__ out_atoms,
                                           float* __restrict__ out2) {
    __shared__ float mean[64];
    int bq = blockIdx.x;
    int t = threadIdx.x;
    float s = 0.f;
    #pragma unroll
    for (int m = 0; m < 8; m++)
        s += out_atoms[(size_t)(bq*8 + m)*64 + t];
    mean[t] = s * 0.125f;
    __syncthreads();
    if (t < 8) {
        float acc = 0.f;
        #pragma unroll
        for (int d = 0; d < 64; d++)
            acc = fmaf(mean[d], Ww[t*64 + d], acc);
        out2[bq*8 + t] = qlw[bq*8 + t] + acc;
    }
}

// ---------------- launch ----------------
extern "C" void kernel_launch(void* const* d_in, const int* in_sizes, int n_in,
                              void* d_out, int out_size) {
    const float* q_atoms   = (const float*)d_in[0];
    const float* q_weights = (const float*)d_in[1];
    const float* q_logw    = (const float*)d_in[2];
    const float* k_atoms   = (const float*)d_in[3];
    const float* k_weights = (const float*)d_in[4];
    const float* v_atoms   = (const float*)d_in[5];
    const float* Wq        = (const float*)d_in[6];
    const float* Wk        = (const float*)d_in[7];
    const float* Wv        = (const float*)d_in[8];
    const float* Wo        = (const float*)d_in[9];
    const float* Ww        = (const float*)d_in[10];
    const float* log_bw    = (const float*)d_in[11];
    const float* log_temp  = (const float*)d_in[12];
    const float* rff_base  = (const float*)d_in[13];

    float* out_atoms = (float*)d_out;
    float* out_lw    = (float*)d_out + (size_t)B_*SQ_*M_*D_;

    cudaFuncSetAttribute(k_flash, cudaFuncAttributeMaxDynamicSharedMemorySize, FLASH_SMEM);

    k_combine<<<H_, 256>>>(Wq, Wk, rff_base, log_bw);
    k_cvt<<<2048, 256>>>(v_atoms, Wv, Wo);
    k_rff<<<dim3(SQ_/16,  BH_), 256>>>(q_atoms, q_weights, 1);
    k_rff<<<dim3(SKV_/16, BH_), 256>>>(k_atoms, k_weights, 0);
    k_va2<<<dim3(4, 256), 256>>>();
    k_flash<<<dim3(4, 8, BH_), 256, FLASH_SMEM>>>(log_temp);
    k_oproj2<<<256, 256>>>(out_atoms);
    k_lw<<<B_*SQ_, 64>>>(Ww, q_logw, out_atoms, out_lw);
}